// round 1
// baseline (speedup 1.0000x reference)
#include <cuda_runtime.h>
#include <math.h>

#define NB 32768      // tokens
#define ND 768        // model dim
#define NH 3072       // hidden dim
#define NE 8          // experts
#define BM 128
#define BN 128
#define BK 8
#define MAX_TILES ((NB * 2) / BM + NE)   // 512 + 8 = 520
#define PAD_ROWS (MAX_TILES * BM)        // 66560

// ---------------- scratch (device globals; no allocation allowed) ----------
__device__ float g_h[(size_t)PAD_ROWS * NH];       // expert-hidden activations
__device__ float g_outp[(size_t)PAD_ROWS * ND];    // per-pair expert outputs
__device__ int   g_pair_token[PAD_ROWS];
__device__ int   g_pairpos[NB * 2];
__device__ float g_wts[NB * 2];
__device__ int   g_eidx[NB * 2];
__device__ int   g_counts[NE];
__device__ int   g_cursor[NE];
__device__ int   g_offsets[NE];
__device__ int   g_tile_expert[MAX_TILES];
__device__ int   g_tile_segend[MAX_TILES];

// ---------------- init ------------------------------------------------------
__global__ void init_kernel() {
    if (threadIdx.x < NE) g_counts[threadIdx.x] = 0;
}

// ---------------- gating: one warp per token -------------------------------
__global__ void gating_kernel(const float* __restrict__ x,
                              const float* __restrict__ Wg,
                              const float* __restrict__ bg) {
    int warp = (blockIdx.x * blockDim.x + threadIdx.x) >> 5;
    int lane = threadIdx.x & 31;
    if (warp >= NB) return;
    const float* xr = x + (size_t)warp * ND;

    float acc[8];
#pragma unroll
    for (int i = 0; i < 8; ++i) acc[i] = 0.f;

#pragma unroll 4
    for (int j = 0; j < ND / 32; ++j) {
        int d = j * 32 + lane;
        float xv = xr[d];
        const float* wr = Wg + (size_t)d * NE;
        float4 w0 = *(const float4*)(wr);
        float4 w1 = *(const float4*)(wr + 4);
        acc[0] += xv * w0.x; acc[1] += xv * w0.y;
        acc[2] += xv * w0.z; acc[3] += xv * w0.w;
        acc[4] += xv * w1.x; acc[5] += xv * w1.y;
        acc[6] += xv * w1.z; acc[7] += xv * w1.w;
    }
#pragma unroll
    for (int i = 0; i < 8; ++i) {
#pragma unroll
        for (int off = 16; off > 0; off >>= 1)
            acc[i] += __shfl_xor_sync(0xFFFFFFFFu, acc[i], off);
    }
    if (lane == 0) {
        float l[8];
#pragma unroll
        for (int i = 0; i < 8; ++i) l[i] = acc[i] + bg[i];
        int e0 = 0; float v0 = l[0];
#pragma unroll
        for (int i = 1; i < 8; ++i)
            if (l[i] > v0) { v0 = l[i]; e0 = i; }
        int e1 = -1; float v1 = -1e30f;
#pragma unroll
        for (int i = 0; i < 8; ++i)
            if (i != e0 && l[i] > v1) { v1 = l[i]; e1 = i; }
        // softmax over the two top values (v0 >= v1)
        float t  = expf(v1 - v0);
        float w0 = 1.f / (1.f + t);
        float w1 = t / (1.f + t);
        g_eidx[warp * 2 + 0] = e0;
        g_eidx[warp * 2 + 1] = e1;
        g_wts[warp * 2 + 0]  = w0;
        g_wts[warp * 2 + 1]  = w1;
        atomicAdd(&g_counts[e0], 1);
        atomicAdd(&g_counts[e1], 1);
    }
}

// ---------------- build aligned segments + tile table -----------------------
__global__ void route_build_kernel() {
    if (threadIdx.x == 0 && blockIdx.x == 0) {
        int off = 0, tile = 0;
        for (int e = 0; e < NE; ++e) {
            g_offsets[e] = off;
            g_cursor[e]  = 0;
            int c  = g_counts[e];
            int nt = (c + BM - 1) / BM;
            for (int i = 0; i < nt; ++i) {
                g_tile_expert[tile] = e;
                g_tile_segend[tile] = off + c;
                ++tile;
            }
            off += nt * BM;
        }
        for (; tile < MAX_TILES; ++tile) g_tile_expert[tile] = -1;
    }
}

// ---------------- assign pair slots -----------------------------------------
__global__ void assign_kernel() {
    int tid = blockIdx.x * blockDim.x + threadIdx.x;
    if (tid >= NB * 2) return;
    int b = tid >> 1;
    int e = g_eidx[tid];
    int pos = g_offsets[e] + atomicAdd(&g_cursor[e], 1);
    g_pair_token[pos] = b;
    g_pairpos[tid]    = pos;
}

// ---------------- GEMM1: h = relu(x[gather] @ W1[e] + b1[e]) ----------------
__global__ __launch_bounds__(256) void gemm1_kernel(const float* __restrict__ x,
                                                    const float* __restrict__ W1,
                                                    const float* __restrict__ b1) {
    int rt = blockIdx.y;
    int e  = g_tile_expert[rt];
    if (e < 0) return;
    int seg_end = g_tile_segend[rt];
    int r0 = rt * BM;
    int n0 = blockIdx.x * BN;

    __shared__ float As[2][BK][BM];
    __shared__ float Bs[2][BK][BN];
    __shared__ int   tok[BM];

    int t = threadIdx.x;
    if (t < BM) {
        int r = r0 + t;
        tok[t] = (r < seg_end) ? g_pair_token[r] : -1;
    }
    __syncthreads();

    const float* Bmat = W1 + (size_t)e * ND * NH;
    int tx = t & 15, ty = t >> 4;
    int am = t >> 1;
    int ak = (t & 1) * 4;
    int bk = t >> 5;
    int bn = (t & 31) * 4;
    int atok = tok[am];
    const float* aptr = x + (size_t)(atok < 0 ? 0 : atok) * ND + ak;
    const float* bptr = Bmat + (size_t)bk * NH + n0 + bn;

    float acc[8][8];
#pragma unroll
    for (int i = 0; i < 8; ++i)
#pragma unroll
        for (int j = 0; j < 8; ++j) acc[i][j] = 0.f;

    float4 zero4 = make_float4(0.f, 0.f, 0.f, 0.f);
    float4 av = (atok >= 0) ? *(const float4*)aptr : zero4;
    float4 bv = *(const float4*)bptr;
    As[0][ak + 0][am] = av.x; As[0][ak + 1][am] = av.y;
    As[0][ak + 2][am] = av.z; As[0][ak + 3][am] = av.w;
    *(float4*)&Bs[0][bk][bn] = bv;
    __syncthreads();

    int buf = 0;
    const int KT = ND / BK;
    for (int kt = 0; kt < KT; ++kt) {
        float4 av2 = zero4, bv2 = zero4;
        if (kt + 1 < KT) {
            if (atok >= 0) av2 = *(const float4*)(aptr + (kt + 1) * BK);
            bv2 = *(const float4*)(bptr + (size_t)(kt + 1) * BK * NH);
        }
#pragma unroll
        for (int k = 0; k < BK; ++k) {
            float a[8], b[8];
            *(float4*)&a[0] = *(const float4*)&As[buf][k][ty * 8];
            *(float4*)&a[4] = *(const float4*)&As[buf][k][ty * 8 + 4];
            *(float4*)&b[0] = *(const float4*)&Bs[buf][k][tx * 8];
            *(float4*)&b[4] = *(const float4*)&Bs[buf][k][tx * 8 + 4];
#pragma unroll
            for (int i = 0; i < 8; ++i)
#pragma unroll
                for (int j = 0; j < 8; ++j) acc[i][j] += a[i] * b[j];
        }
        if (kt + 1 < KT) {
            int nb = buf ^ 1;
            As[nb][ak + 0][am] = av2.x; As[nb][ak + 1][am] = av2.y;
            As[nb][ak + 2][am] = av2.z; As[nb][ak + 3][am] = av2.w;
            *(float4*)&Bs[nb][bk][bn] = bv2;
        }
        __syncthreads();
        buf ^= 1;
    }

    const float* b1e = b1 + (size_t)e * NH + n0 + tx * 8;
    float bias[8];
#pragma unroll
    for (int j = 0; j < 8; ++j) bias[j] = b1e[j];
#pragma unroll
    for (int i = 0; i < 8; ++i) {
        int r = r0 + ty * 8 + i;
        if (r < seg_end) {
            float* hp = g_h + (size_t)r * NH + n0 + tx * 8;
            float4 v0, v1;
            v0.x = fmaxf(acc[i][0] + bias[0], 0.f);
            v0.y = fmaxf(acc[i][1] + bias[1], 0.f);
            v0.z = fmaxf(acc[i][2] + bias[2], 0.f);
            v0.w = fmaxf(acc[i][3] + bias[3], 0.f);
            v1.x = fmaxf(acc[i][4] + bias[4], 0.f);
            v1.y = fmaxf(acc[i][5] + bias[5], 0.f);
            v1.z = fmaxf(acc[i][6] + bias[6], 0.f);
            v1.w = fmaxf(acc[i][7] + bias[7], 0.f);
            *(float4*)hp       = v0;
            *(float4*)(hp + 4) = v1;
        }
    }
}

// ---------------- GEMM2: out = h @ W2[e] + b2[e] -----------------------------
__global__ __launch_bounds__(256) void gemm2_kernel(const float* __restrict__ W2,
                                                    const float* __restrict__ b2) {
    int rt = blockIdx.y;
    int e  = g_tile_expert[rt];
    if (e < 0) return;
    int seg_end = g_tile_segend[rt];
    int r0 = rt * BM;
    int n0 = blockIdx.x * BN;

    __shared__ float As[2][BK][BM];
    __shared__ float Bs[2][BK][BN];

    int t = threadIdx.x;
    const float* Bmat = W2 + (size_t)e * NH * ND;
    int tx = t & 15, ty = t >> 4;
    int am = t >> 1;
    int ak = (t & 1) * 4;
    int bk = t >> 5;
    int bn = (t & 31) * 4;
    int arow = r0 + am;
    int avalid = (arow < seg_end);
    const float* aptr = g_h + (size_t)arow * NH + ak;
    const float* bptr = Bmat + (size_t)bk * ND + n0 + bn;

    float acc[8][8];
#pragma unroll
    for (int i = 0; i < 8; ++i)
#pragma unroll
        for (int j = 0; j < 8; ++j) acc[i][j] = 0.f;

    float4 zero4 = make_float4(0.f, 0.f, 0.f, 0.f);
    float4 av = avalid ? *(const float4*)aptr : zero4;
    float4 bv = *(const float4*)bptr;
    As[0][ak + 0][am] = av.x; As[0][ak + 1][am] = av.y;
    As[0][ak + 2][am] = av.z; As[0][ak + 3][am] = av.w;
    *(float4*)&Bs[0][bk][bn] = bv;
    __syncthreads();

    int buf = 0;
    const int KT = NH / BK;
    for (int kt = 0; kt < KT; ++kt) {
        float4 av2 = zero4, bv2 = zero4;
        if (kt + 1 < KT) {
            if (avalid) av2 = *(const float4*)(aptr + (kt + 1) * BK);
            bv2 = *(const float4*)(bptr + (size_t)(kt + 1) * BK * ND);
        }
#pragma unroll
        for (int k = 0; k < BK; ++k) {
            float a[8], b[8];
            *(float4*)&a[0] = *(const float4*)&As[buf][k][ty * 8];
            *(float4*)&a[4] = *(const float4*)&As[buf][k][ty * 8 + 4];
            *(float4*)&b[0] = *(const float4*)&Bs[buf][k][tx * 8];
            *(float4*)&b[4] = *(const float4*)&Bs[buf][k][tx * 8 + 4];
#pragma unroll
            for (int i = 0; i < 8; ++i)
#pragma unroll
                for (int j = 0; j < 8; ++j) acc[i][j] += a[i] * b[j];
        }
        if (kt + 1 < KT) {
            int nb = buf ^ 1;
            As[nb][ak + 0][am] = av2.x; As[nb][ak + 1][am] = av2.y;
            As[nb][ak + 2][am] = av2.z; As[nb][ak + 3][am] = av2.w;
            *(float4*)&Bs[nb][bk][bn] = bv2;
        }
        __syncthreads();
        buf ^= 1;
    }

    const float* b2e = b2 + (size_t)e * ND + n0 + tx * 8;
    float bias[8];
#pragma unroll
    for (int j = 0; j < 8; ++j) bias[j] = b2e[j];
#pragma unroll
    for (int i = 0; i < 8; ++i) {
        int r = r0 + ty * 8 + i;
        if (r < seg_end) {
            float* op = g_outp + (size_t)r * ND + n0 + tx * 8;
            float4 v0, v1;
            v0.x = acc[i][0] + bias[0];
            v0.y = acc[i][1] + bias[1];
            v0.z = acc[i][2] + bias[2];
            v0.w = acc[i][3] + bias[3];
            v1.x = acc[i][4] + bias[4];
            v1.y = acc[i][5] + bias[5];
            v1.z = acc[i][6] + bias[6];
            v1.w = acc[i][7] + bias[7];
            *(float4*)op       = v0;
            *(float4*)(op + 4) = v1;
        }
    }
}

// ---------------- combine: y[b] = w0*out[p0] + w1*out[p1] -------------------
__global__ void combine_kernel(float* __restrict__ y) {
    const int QD = ND / 4;
    int tid = blockIdx.x * blockDim.x + threadIdx.x;
    if (tid >= NB * QD) return;
    int b = tid / QD;
    int q = tid - b * QD;
    int p0 = g_pairpos[b * 2 + 0];
    int p1 = g_pairpos[b * 2 + 1];
    float w0 = g_wts[b * 2 + 0];
    float w1 = g_wts[b * 2 + 1];
    float4 o0 = ((const float4*)(g_outp + (size_t)p0 * ND))[q];
    float4 o1 = ((const float4*)(g_outp + (size_t)p1 * ND))[q];
    float4 r;
    r.x = w0 * o0.x + w1 * o1.x;
    r.y = w0 * o0.y + w1 * o1.y;
    r.z = w0 * o0.z + w1 * o1.z;
    r.w = w0 * o0.w + w1 * o1.w;
    ((float4*)y)[tid] = r;
}

// ---------------- launch ----------------------------------------------------
extern "C" void kernel_launch(void* const* d_in, const int* in_sizes, int n_in,
                              void* d_out, int out_size) {
    const float* x  = (const float*)d_in[0];
    const float* Wg = (const float*)d_in[1];
    const float* bg = (const float*)d_in[2];
    const float* W1 = (const float*)d_in[3];
    const float* b1 = (const float*)d_in[4];
    const float* W2 = (const float*)d_in[5];
    const float* b2 = (const float*)d_in[6];
    float* y = (float*)d_out;

    init_kernel<<<1, 32>>>();
    gating_kernel<<<(NB * 32) / 256, 256>>>(x, Wg, bg);
    route_build_kernel<<<1, 1>>>();
    assign_kernel<<<(NB * 2) / 256, 256>>>();

    dim3 g1(NH / BN, MAX_TILES);
    gemm1_kernel<<<g1, 256>>>(x, W1, b1);

    dim3 g2(ND / BN, MAX_TILES);
    gemm2_kernel<<<g2, 256>>>(W2, b2);

    combine_kernel<<<(NB * (ND / 4) + 255) / 256, 256>>>(y);
}

// round 6
// speedup vs baseline: 1.0528x; 1.0528x over previous
#include <cuda_runtime.h>
#include <math.h>

#define NB 32768      // tokens
#define ND 768        // model dim
#define NH 3072       // hidden dim
#define NE 8          // experts
#define BM 128
#define BN 128
#define BK 8
#define MAX_TILES ((NB * 2) / BM + NE)   // 512 + 8 = 520
#define PAD_ROWS (MAX_TILES * BM)        // 66560

// ---------------- scratch (device globals; no allocation allowed) ----------
__device__ float g_h[(size_t)PAD_ROWS * NH];       // expert-hidden activations
__device__ float g_outp[(size_t)PAD_ROWS * ND];    // per-pair expert outputs
__device__ int   g_pair_token[PAD_ROWS];
__device__ int   g_pairpos[NB * 2];
__device__ float g_wts[NB * 2];
__device__ int   g_eidx[NB * 2];
__device__ int   g_counts[NE];
__device__ int   g_cursor[NE];
__device__ int   g_offsets[NE];
__device__ int   g_tile_expert[MAX_TILES];
__device__ int   g_tile_segend[MAX_TILES];

// ---------------- packed f32x2 helpers (Blackwell FFMA2 path) ---------------
typedef unsigned long long u64t;
#define FMA2(acc, a, b) \
    asm("fma.rn.f32x2 %0, %1, %2, %0;" : "+l"(acc) : "l"(a), "l"(b))
#define PACK_DUP(d, s_uint) \
    asm("mov.b64 %0, {%1, %1};" : "=l"(d) : "r"(s_uint))
#define UNPK(lo, hi, s) \
    asm("mov.b64 {%0, %1}, %2;" : "=f"(lo), "=f"(hi) : "l"(s))

// ---------------- init ------------------------------------------------------
__global__ void init_kernel() {
    if (threadIdx.x < NE) g_counts[threadIdx.x] = 0;
}

// ---------------- gating: one warp per token -------------------------------
__global__ void gating_kernel(const float* __restrict__ x,
                              const float* __restrict__ Wg,
                              const float* __restrict__ bg) {
    int warp = (blockIdx.x * blockDim.x + threadIdx.x) >> 5;
    int lane = threadIdx.x & 31;
    if (warp >= NB) return;
    const float* xr = x + (size_t)warp * ND;

    float acc[8];
#pragma unroll
    for (int i = 0; i < 8; ++i) acc[i] = 0.f;

#pragma unroll 4
    for (int j = 0; j < ND / 32; ++j) {
        int d = j * 32 + lane;
        float xv = xr[d];
        const float* wr = Wg + (size_t)d * NE;
        float4 w0 = *(const float4*)(wr);
        float4 w1 = *(const float4*)(wr + 4);
        acc[0] += xv * w0.x; acc[1] += xv * w0.y;
        acc[2] += xv * w0.z; acc[3] += xv * w0.w;
        acc[4] += xv * w1.x; acc[5] += xv * w1.y;
        acc[6] += xv * w1.z; acc[7] += xv * w1.w;
    }
#pragma unroll
    for (int i = 0; i < 8; ++i) {
#pragma unroll
        for (int off = 16; off > 0; off >>= 1)
            acc[i] += __shfl_xor_sync(0xFFFFFFFFu, acc[i], off);
    }
    if (lane == 0) {
        float l[8];
#pragma unroll
        for (int i = 0; i < 8; ++i) l[i] = acc[i] + bg[i];
        int e0 = 0; float v0 = l[0];
#pragma unroll
        for (int i = 1; i < 8; ++i)
            if (l[i] > v0) { v0 = l[i]; e0 = i; }
        int e1 = -1; float v1 = -1e30f;
#pragma unroll
        for (int i = 0; i < 8; ++i)
            if (i != e0 && l[i] > v1) { v1 = l[i]; e1 = i; }
        // softmax over the two top values (v0 >= v1)
        float t  = expf(v1 - v0);
        float w0 = 1.f / (1.f + t);
        float w1 = t / (1.f + t);
        g_eidx[warp * 2 + 0] = e0;
        g_eidx[warp * 2 + 1] = e1;
        g_wts[warp * 2 + 0]  = w0;
        g_wts[warp * 2 + 1]  = w1;
        atomicAdd(&g_counts[e0], 1);
        atomicAdd(&g_counts[e1], 1);
    }
}

// ---------------- build aligned segments + tile table -----------------------
__global__ void route_build_kernel() {
    if (threadIdx.x == 0 && blockIdx.x == 0) {
        int off = 0, tile = 0;
        for (int e = 0; e < NE; ++e) {
            g_offsets[e] = off;
            g_cursor[e]  = 0;
            int c  = g_counts[e];
            int nt = (c + BM - 1) / BM;
            for (int i = 0; i < nt; ++i) {
                g_tile_expert[tile] = e;
                g_tile_segend[tile] = off + c;
                ++tile;
            }
            off += nt * BM;
        }
        for (; tile < MAX_TILES; ++tile) g_tile_expert[tile] = -1;
    }
}

// ---------------- assign pair slots -----------------------------------------
__global__ void assign_kernel() {
    int tid = blockIdx.x * blockDim.x + threadIdx.x;
    if (tid >= NB * 2) return;
    int b = tid >> 1;
    int e = g_eidx[tid];
    int pos = g_offsets[e] + atomicAdd(&g_cursor[e], 1);
    g_pair_token[pos] = b;
    g_pairpos[tid]    = pos;
}

// ---------------- GEMM1: h = relu(x[gather] @ W1[e] + b1[e]) ----------------
__global__ __launch_bounds__(256) void gemm1_kernel(const float* __restrict__ x,
                                                    const float* __restrict__ W1,
                                                    const float* __restrict__ b1) {
    int rt = blockIdx.y;
    int e  = g_tile_expert[rt];
    if (e < 0) return;
    int seg_end = g_tile_segend[rt];
    int r0 = rt * BM;
    int n0 = blockIdx.x * BN;

    __shared__ float As[2][BK][BM];
    __shared__ float Bs[2][BK][BN];
    __shared__ int   tok[BM];

    int t = threadIdx.x;
    if (t < BM) {
        int r = r0 + t;
        tok[t] = (r < seg_end) ? g_pair_token[r] : -1;
    }
    __syncthreads();

    const float* Bmat = W1 + (size_t)e * ND * NH;
    int tx = t & 15, ty = t >> 4;
    int am = t >> 1;
    int ak = (t & 1) * 4;
    int bk = t >> 5;
    int bn = (t & 31) * 4;
    int atok = tok[am];
    const float* aptr = x + (size_t)(atok < 0 ? 0 : atok) * ND + ak;
    const float* bptr = Bmat + (size_t)bk * NH + n0 + bn;

    // packed accumulators: acc2[q][j] = {acc[2q][j], acc[2q+1][j]}
    u64t acc2[4][8];
#pragma unroll
    for (int q = 0; q < 4; ++q)
#pragma unroll
        for (int j = 0; j < 8; ++j) acc2[q][j] = 0ull;

    float4 zero4 = make_float4(0.f, 0.f, 0.f, 0.f);
    float4 av = (atok >= 0) ? *(const float4*)aptr : zero4;
    float4 bv = *(const float4*)bptr;
    As[0][ak + 0][am] = av.x; As[0][ak + 1][am] = av.y;
    As[0][ak + 2][am] = av.z; As[0][ak + 3][am] = av.w;
    *(float4*)&Bs[0][bk][bn] = bv;
    __syncthreads();

    int buf = 0;
    const int KT = ND / BK;
    for (int kt = 0; kt < KT; ++kt) {
        float4 av2 = zero4, bv2 = zero4;
        if (kt + 1 < KT) {
            if (atok >= 0) av2 = *(const float4*)(aptr + (kt + 1) * BK);
            bv2 = *(const float4*)(bptr + (size_t)(kt + 1) * BK * NH);
        }
#pragma unroll
        for (int k = 0; k < BK; ++k) {
            // A as packed m-pairs: direct 64-bit shared loads (32B-aligned)
            u64t a2[4];
#pragma unroll
            for (int q = 0; q < 4; ++q)
                a2[q] = *(const u64t*)&As[buf][k][ty * 8 + q * 2];
            float b[8];
            *(float4*)&b[0] = *(const float4*)&Bs[buf][k][tx * 8];
            *(float4*)&b[4] = *(const float4*)&Bs[buf][k][tx * 8 + 4];
            u64t bb[8];
#pragma unroll
            for (int j = 0; j < 8; ++j) PACK_DUP(bb[j], __float_as_uint(b[j]));
#pragma unroll
            for (int q = 0; q < 4; ++q)
#pragma unroll
                for (int j = 0; j < 8; ++j) FMA2(acc2[q][j], a2[q], bb[j]);
        }
        if (kt + 1 < KT) {
            int nb = buf ^ 1;
            As[nb][ak + 0][am] = av2.x; As[nb][ak + 1][am] = av2.y;
            As[nb][ak + 2][am] = av2.z; As[nb][ak + 3][am] = av2.w;
            *(float4*)&Bs[nb][bk][bn] = bv2;
        }
        __syncthreads();
        buf ^= 1;
    }

    const float* b1e = b1 + (size_t)e * NH + n0 + tx * 8;
    float bias[8];
#pragma unroll
    for (int j = 0; j < 8; ++j) bias[j] = b1e[j];
#pragma unroll
    for (int q = 0; q < 4; ++q) {
        float rowlo[8], rowhi[8];
#pragma unroll
        for (int j = 0; j < 8; ++j) UNPK(rowlo[j], rowhi[j], acc2[q][j]);
#pragma unroll
        for (int h = 0; h < 2; ++h) {
            const float* rowv = h ? rowhi : rowlo;
            int r = r0 + ty * 8 + q * 2 + h;
            if (r < seg_end) {
                float* hp = g_h + (size_t)r * NH + n0 + tx * 8;
                float4 v0, v1;
                v0.x = fmaxf(rowv[0] + bias[0], 0.f);
                v0.y = fmaxf(rowv[1] + bias[1], 0.f);
                v0.z = fmaxf(rowv[2] + bias[2], 0.f);
                v0.w = fmaxf(rowv[3] + bias[3], 0.f);
                v1.x = fmaxf(rowv[4] + bias[4], 0.f);
                v1.y = fmaxf(rowv[5] + bias[5], 0.f);
                v1.z = fmaxf(rowv[6] + bias[6], 0.f);
                v1.w = fmaxf(rowv[7] + bias[7], 0.f);
                *(float4*)hp       = v0;
                *(float4*)(hp + 4) = v1;
            }
        }
    }
}

// ---------------- GEMM2: out = h @ W2[e] + b2[e] -----------------------------
__global__ __launch_bounds__(256) void gemm2_kernel(const float* __restrict__ W2,
                                                    const float* __restrict__ b2) {
    int rt = blockIdx.y;
    int e  = g_tile_expert[rt];
    if (e < 0) return;
    int seg_end = g_tile_segend[rt];
    int r0 = rt * BM;
    int n0 = blockIdx.x * BN;

    __shared__ float As[2][BK][BM];
    __shared__ float Bs[2][BK][BN];

    int t = threadIdx.x;
    const float* Bmat = W2 + (size_t)e * NH * ND;
    int tx = t & 15, ty = t >> 4;
    int am = t >> 1;
    int ak = (t & 1) * 4;
    int bk = t >> 5;
    int bn = (t & 31) * 4;
    int arow = r0 + am;
    int avalid = (arow < seg_end);
    const float* aptr = g_h + (size_t)arow * NH + ak;
    const float* bptr = Bmat + (size_t)bk * ND + n0 + bn;

    u64t acc2[4][8];
#pragma unroll
    for (int q = 0; q < 4; ++q)
#pragma unroll
        for (int j = 0; j < 8; ++j) acc2[q][j] = 0ull;

    float4 zero4 = make_float4(0.f, 0.f, 0.f, 0.f);
    float4 av = avalid ? *(const float4*)aptr : zero4;
    float4 bv = *(const float4*)bptr;
    As[0][ak + 0][am] = av.x; As[0][ak + 1][am] = av.y;
    As[0][ak + 2][am] = av.z; As[0][ak + 3][am] = av.w;
    *(float4*)&Bs[0][bk][bn] = bv;
    __syncthreads();

    int buf = 0;
    const int KT = NH / BK;
    for (int kt = 0; kt < KT; ++kt) {
        float4 av2 = zero4, bv2 = zero4;
        if (kt + 1 < KT) {
            if (avalid) av2 = *(const float4*)(aptr + (kt + 1) * BK);
            bv2 = *(const float4*)(bptr + (size_t)(kt + 1) * BK * ND);
        }
#pragma unroll
        for (int k = 0; k < BK; ++k) {
            u64t a2[4];
#pragma unroll
            for (int q = 0; q < 4; ++q)
                a2[q] = *(const u64t*)&As[buf][k][ty * 8 + q * 2];
            float b[8];
            *(float4*)&b[0] = *(const float4*)&Bs[buf][k][tx * 8];
            *(float4*)&b[4] = *(const float4*)&Bs[buf][k][tx * 8 + 4];
            u64t bb[8];
#pragma unroll
            for (int j = 0; j < 8; ++j) PACK_DUP(bb[j], __float_as_uint(b[j]));
#pragma unroll
            for (int q = 0; q < 4; ++q)
#pragma unroll
                for (int j = 0; j < 8; ++j) FMA2(acc2[q][j], a2[q], bb[j]);
        }
        if (kt + 1 < KT) {
            int nb = buf ^ 1;
            As[nb][ak + 0][am] = av2.x; As[nb][ak + 1][am] = av2.y;
            As[nb][ak + 2][am] = av2.z; As[nb][ak + 3][am] = av2.w;
            *(float4*)&Bs[nb][bk][bn] = bv2;
        }
        __syncthreads();
        buf ^= 1;
    }

    const float* b2e = b2 + (size_t)e * ND + n0 + tx * 8;
    float bias[8];
#pragma unroll
    for (int j = 0; j < 8; ++j) bias[j] = b2e[j];
#pragma unroll
    for (int q = 0; q < 4; ++q) {
        float rowlo[8], rowhi[8];
#pragma unroll
        for (int j = 0; j < 8; ++j) UNPK(rowlo[j], rowhi[j], acc2[q][j]);
#pragma unroll
        for (int h = 0; h < 2; ++h) {
            const float* rowv = h ? rowhi : rowlo;
            int r = r0 + ty * 8 + q * 2 + h;
            if (r < seg_end) {
                float* op = g_outp + (size_t)r * ND + n0 + tx * 8;
                float4 v0, v1;
                v0.x = rowv[0] + bias[0];
                v0.y = rowv[1] + bias[1];
                v0.z = rowv[2] + bias[2];
                v0.w = rowv[3] + bias[3];
                v1.x = rowv[4] + bias[4];
                v1.y = rowv[5] + bias[5];
                v1.z = rowv[6] + bias[6];
                v1.w = rowv[7] + bias[7];
                *(float4*)op       = v0;
                *(float4*)(op + 4) = v1;
            }
        }
    }
}

// ---------------- combine: y[b] = w0*out[p0] + w1*out[p1] -------------------
__global__ void combine_kernel(float* __restrict__ y) {
    const int QD = ND / 4;
    int tid = blockIdx.x * blockDim.x + threadIdx.x;
    if (tid >= NB * QD) return;
    int b = tid / QD;
    int q = tid - b * QD;
    int p0 = g_pairpos[b * 2 + 0];
    int p1 = g_pairpos[b * 2 + 1];
    float w0 = g_wts[b * 2 + 0];
    float w1 = g_wts[b * 2 + 1];
    float4 o0 = ((const float4*)(g_outp + (size_t)p0 * ND))[q];
    float4 o1 = ((const float4*)(g_outp + (size_t)p1 * ND))[q];
    float4 r;
    r.x = w0 * o0.x + w1 * o1.x;
    r.y = w0 * o0.y + w1 * o1.y;
    r.z = w0 * o0.z + w1 * o1.z;
    r.w = w0 * o0.w + w1 * o1.w;
    ((float4*)y)[tid] = r;
}

// ---------------- launch ----------------------------------------------------
extern "C" void kernel_launch(void* const* d_in, const int* in_sizes, int n_in,
                              void* d_out, int out_size) {
    const float* x  = (const float*)d_in[0];
    const float* Wg = (const float*)d_in[1];
    const float* bg = (const float*)d_in[2];
    const float* W1 = (const float*)d_in[3];
    const float* b1 = (const float*)d_in[4];
    const float* W2 = (const float*)d_in[5];
    const float* b2 = (const float*)d_in[6];
    float* y = (float*)d_out;

    init_kernel<<<1, 32>>>();
    gating_kernel<<<(NB * 32) / 256, 256>>>(x, Wg, bg);
    route_build_kernel<<<1, 1>>>();
    assign_kernel<<<(NB * 2) / 256, 256>>>();

    dim3 g1(NH / BN, MAX_TILES);
    gemm1_kernel<<<g1, 256>>>(x, W1, b1);

    dim3 g2(ND / BN, MAX_TILES);
    gemm2_kernel<<<g2, 256>>>(W2, b2);

    combine_kernel<<<(NB * (ND / 4) + 255) / 256, 256>>>(y);
}

// round 10
// speedup vs baseline: 2.0976x; 1.9924x over previous
#include <cuda_runtime.h>
#include <cuda_bf16.h>
#include <cstdint>
#include <math.h>

#define NB 32768      // tokens
#define ND 768        // model dim
#define NH 3072       // hidden dim
#define NE 8          // experts
#define BM 128
#define BN 128
#define BK 16
#define MAX_TILES ((NB * 2) / BM + NE)   // 520
#define PAD_ROWS (MAX_TILES * BM)        // 66560

#define A_LD 24       // A smem row stride (elements): 16 data + 8 pad = 48B
#define B_LD 136      // B smem row stride (elements): 128 data + 8 pad = 272B

// ---------------- scratch (device globals; no allocation allowed) ----------
// NOTE: these are referenced ONLY inside device code (never passed as kernel
// arguments from host code) — passing a __device__ symbol from host gives the
// host-side shadow address, which was the root cause of the R3-R9 failures.
__device__ float g_h[(size_t)PAD_ROWS * NH];       // expert-hidden activations (fp32)
__device__ float g_outp[(size_t)PAD_ROWS * ND];    // per-pair expert outputs
__device__ int   g_pair_token[PAD_ROWS];
__device__ int   g_pairpos[NB * 2];
__device__ float g_wts[NB * 2];
__device__ int   g_eidx[NB * 2];
__device__ int   g_counts[NE];
__device__ int   g_cursor[NE];
__device__ int   g_offsets[NE];
__device__ int   g_tile_expert[MAX_TILES];
__device__ int   g_tile_segend[MAX_TILES];

// ---------------- manual m16n8k16 bf16 mma ----------------------------------
#define MMA_BF16(d, a, b) \
    asm volatile("mma.sync.aligned.m16n8k16.row.col.f32.bf16.bf16.f32 " \
        "{%0,%1,%2,%3}, {%4,%5,%6,%7}, {%8,%9}, {%0,%1,%2,%3};" \
        : "+f"((d)[0]), "+f"((d)[1]), "+f"((d)[2]), "+f"((d)[3]) \
        : "r"((a)[0]), "r"((a)[1]), "r"((a)[2]), "r"((a)[3]), \
          "r"((b)[0]), "r"((b)[1]))

// ---------------- init / gating / routing (R1/R6-proven) --------------------
__global__ void init_kernel() {
    if (threadIdx.x < NE) g_counts[threadIdx.x] = 0;
}

__global__ void gating_kernel(const float* __restrict__ x,
                              const float* __restrict__ Wg,
                              const float* __restrict__ bg) {
    int warp = (blockIdx.x * blockDim.x + threadIdx.x) >> 5;
    int lane = threadIdx.x & 31;
    if (warp >= NB) return;
    const float* xr = x + (size_t)warp * ND;
    float acc[8];
#pragma unroll
    for (int i = 0; i < 8; ++i) acc[i] = 0.f;
#pragma unroll 4
    for (int j = 0; j < ND / 32; ++j) {
        int d = j * 32 + lane;
        float xv = xr[d];
        const float* wr = Wg + (size_t)d * NE;
        float4 w0 = *(const float4*)(wr);
        float4 w1 = *(const float4*)(wr + 4);
        acc[0] += xv * w0.x; acc[1] += xv * w0.y;
        acc[2] += xv * w0.z; acc[3] += xv * w0.w;
        acc[4] += xv * w1.x; acc[5] += xv * w1.y;
        acc[6] += xv * w1.z; acc[7] += xv * w1.w;
    }
#pragma unroll
    for (int i = 0; i < 8; ++i)
#pragma unroll
        for (int off = 16; off > 0; off >>= 1)
            acc[i] += __shfl_xor_sync(0xFFFFFFFFu, acc[i], off);
    if (lane == 0) {
        float l[8];
#pragma unroll
        for (int i = 0; i < 8; ++i) l[i] = acc[i] + bg[i];
        int e0 = 0; float v0 = l[0];
#pragma unroll
        for (int i = 1; i < 8; ++i)
            if (l[i] > v0) { v0 = l[i]; e0 = i; }
        int e1 = -1; float v1 = -1e30f;
#pragma unroll
        for (int i = 0; i < 8; ++i)
            if (i != e0 && l[i] > v1) { v1 = l[i]; e1 = i; }
        float t  = expf(v1 - v0);
        float w0 = 1.f / (1.f + t);
        float w1 = t / (1.f + t);
        g_eidx[warp * 2 + 0] = e0;
        g_eidx[warp * 2 + 1] = e1;
        g_wts[warp * 2 + 0]  = w0;
        g_wts[warp * 2 + 1]  = w1;
        atomicAdd(&g_counts[e0], 1);
        atomicAdd(&g_counts[e1], 1);
    }
}

__global__ void route_build_kernel() {
    if (threadIdx.x == 0 && blockIdx.x == 0) {
        int off = 0, tile = 0;
        for (int e = 0; e < NE; ++e) {
            g_offsets[e] = off;
            g_cursor[e]  = 0;
            int c  = g_counts[e];
            int nt = (c + BM - 1) / BM;
            for (int i = 0; i < nt; ++i) {
                g_tile_expert[tile] = e;
                g_tile_segend[tile] = off + c;
                ++tile;
            }
            off += nt * BM;
        }
        for (; tile < MAX_TILES; ++tile) { g_tile_expert[tile] = -1; g_tile_segend[tile] = 0; }
    }
}

__global__ void assign_kernel() {
    int tid = blockIdx.x * blockDim.x + threadIdx.x;
    if (tid >= NB * 2) return;
    int b = tid >> 1;
    int e = g_eidx[tid];
    int pos = g_offsets[e] + atomicAdd(&g_cursor[e], 1);
    g_pair_token[pos] = b;
    g_pairpos[tid]    = pos;
}

// ---------------- manual-MMA GEMM --------------------------------------------
// 256 threads = 8 warps in 2(m) x 4(n). Warp tile 64x32.
// A: fp32 rows -> smem bf16 hi/lo [m][k], row-major, A_LD stride.
// B: fp32 [K][N] native -> smem bf16 hi/lo [k][n], B_LD stride.
// Fragments built with plain LDS per the PTX ISA m16n8k16 lane mapping.
// 3 products: Ah*Bh + Ah*Bl + Al*Bh, fp32 accumulate.
// g_h / g_outp / tok are bound INSIDE device code (see note at globals).
template<int KTOT, bool IS_GEMM1>
__global__ __launch_bounds__(256) void gemm_mma_kernel(
    const float* __restrict__ xin,       // x (used by gemm1 only)
    const float* __restrict__ Ball,      // W1 or W2: [E][KTOT][NTOT]
    const float* __restrict__ bias_all,  // [E][NTOT]
    int NTOT) {

    __shared__ __nv_bfloat16 sAh[2][BM * A_LD];
    __shared__ __nv_bfloat16 sAl[2][BM * A_LD];
    __shared__ __nv_bfloat16 sBh[2][BK * B_LD];
    __shared__ __nv_bfloat16 sBl[2][BK * B_LD];
    __shared__ int tok[BM];

    // device-side binding of scratch buffers (the R3-R9 fix)
    const float* Asrc = IS_GEMM1 ? xin : (const float*)g_h;
    float* Out        = IS_GEMM1 ? (float*)g_h : (float*)g_outp;

    int rt = blockIdx.y;
    int e  = g_tile_expert[rt];
    if (e < 0) return;
    int seg_end = g_tile_segend[rt];
    int r0 = rt * BM;
    int n0 = blockIdx.x * BN;

    int t = threadIdx.x;
    int lane = t & 31;
    int warp = t >> 5;
    int m_base = (warp & 1) * 64;
    int n_base = (warp >> 1) * 32;
    int g4   = lane >> 2;   // 0..7
    int tid4 = lane & 3;    // 0..3

    if (IS_GEMM1) {
        if (t < BM) {
            int r = r0 + t;
            tok[t] = (r < seg_end) ? g_pair_token[r] : -1;
        }
        __syncthreads();
    }

    // ---- loaders (plain ld.global -> regs -> smem; no cp.async) ------------
    int row_a = t >> 1;          // 0..127
    int half  = t & 1;
    const float* aptr;
    bool a_valid;
    if (IS_GEMM1) {
        int atok = tok[row_a];
        a_valid = (atok >= 0);
        aptr = Asrc + (size_t)(a_valid ? atok : 0) * KTOT + half * 8;
    } else {
        a_valid = true;          // padded g_h rows are never written -> zero
        aptr = Asrc + (size_t)(r0 + row_a) * KTOT + half * 8;
    }
    int krow = t >> 4;           // 0..15
    int seg  = t & 15;           // 8-float n segment
    const float* bptr = Ball + (size_t)e * KTOT * NTOT + (size_t)krow * NTOT + n0 + seg * 8;
    const float* bias_e = bias_all + (size_t)e * NTOT + n0;

    float ar[8], br[8];
    auto load_regs = [&](int c) {
        if (a_valid) {
            float4 u = *(const float4*)(aptr + c * BK);
            float4 v = *(const float4*)(aptr + c * BK + 4);
            ar[0]=u.x; ar[1]=u.y; ar[2]=u.z; ar[3]=u.w;
            ar[4]=v.x; ar[5]=v.y; ar[6]=v.z; ar[7]=v.w;
        } else {
#pragma unroll
            for (int i = 0; i < 8; ++i) ar[i] = 0.f;
        }
        const float* bp = bptr + (size_t)c * BK * NTOT;
        float4 u = *(const float4*)(bp);
        float4 v = *(const float4*)(bp + 4);
        br[0]=u.x; br[1]=u.y; br[2]=u.z; br[3]=u.w;
        br[4]=v.x; br[5]=v.y; br[6]=v.z; br[7]=v.w;
    };
    auto store_smem = [&](int s) {
        ushort ah[8], al[8], bh[8], bl[8];
#pragma unroll
        for (int i = 0; i < 8; ++i) {
            __nv_bfloat16 h = __float2bfloat16(ar[i]);
            __nv_bfloat16 l = __float2bfloat16(ar[i] - __bfloat162float(h));
            ah[i] = __bfloat16_as_ushort(h);
            al[i] = __bfloat16_as_ushort(l);
            h = __float2bfloat16(br[i]);
            l = __float2bfloat16(br[i] - __bfloat162float(h));
            bh[i] = __bfloat16_as_ushort(h);
            bl[i] = __bfloat16_as_ushort(l);
        }
        *(uint4*)&sAh[s][row_a * A_LD + half * 8] = *(uint4*)ah;
        *(uint4*)&sAl[s][row_a * A_LD + half * 8] = *(uint4*)al;
        *(uint4*)&sBh[s][krow * B_LD + seg * 8]   = *(uint4*)bh;
        *(uint4*)&sBl[s][krow * B_LD + seg * 8]   = *(uint4*)bl;
    };

    float acc[4][4][4];
#pragma unroll
    for (int i = 0; i < 4; ++i)
#pragma unroll
        for (int j = 0; j < 4; ++j)
#pragma unroll
            for (int q = 0; q < 4; ++q) acc[i][j][q] = 0.f;

    const int NC = KTOT / BK;

    load_regs(0);
    store_smem(0);
    __syncthreads();

    for (int c = 0; c < NC; ++c) {
        int s = c & 1;
        if (c + 1 < NC) load_regs(c + 1);

        const __nv_bfloat16* pAh = sAh[s];
        const __nv_bfloat16* pAl = sAl[s];
        const __nv_bfloat16* pBh = sBh[s];
        const __nv_bfloat16* pBl = sBl[s];

        // A fragments (PTX ISA m16n8k16, A row-major):
        // a0:(g,2t) a1:(g+8,2t) a2:(g,2t+8) a3:(g+8,2t+8); pairs k-adjacent
        uint32_t fah[4][4], fal[4][4];
#pragma unroll
        for (int i = 0; i < 4; ++i) {
            int rlo = (m_base + i * 16 + g4) * A_LD + tid4 * 2;
            int rhi = rlo + 8 * A_LD;
            fah[i][0] = *(const uint32_t*)&pAh[rlo];
            fah[i][1] = *(const uint32_t*)&pAh[rhi];
            fah[i][2] = *(const uint32_t*)&pAh[rlo + 8];
            fah[i][3] = *(const uint32_t*)&pAh[rhi + 8];
            fal[i][0] = *(const uint32_t*)&pAl[rlo];
            fal[i][1] = *(const uint32_t*)&pAl[rhi];
            fal[i][2] = *(const uint32_t*)&pAl[rlo + 8];
            fal[i][3] = *(const uint32_t*)&pAl[rhi + 8];
        }
        // B fragments (k16 x n8, .col): b0={B[2t][n],B[2t+1][n]},
        // b1={B[2t+8][n],B[2t+9][n]} — scalar 16-bit loads from [k][n] smem
#pragma unroll
        for (int j = 0; j < 4; ++j) {
            int nn = n_base + j * 8 + g4;
            int k0 = tid4 * 2;
            uint32_t bh[2], bl[2];
            bh[0] = (uint32_t)__bfloat16_as_ushort(pBh[k0 * B_LD + nn]) |
                    ((uint32_t)__bfloat16_as_ushort(pBh[(k0 + 1) * B_LD + nn]) << 16);
            bh[1] = (uint32_t)__bfloat16_as_ushort(pBh[(k0 + 8) * B_LD + nn]) |
                    ((uint32_t)__bfloat16_as_ushort(pBh[(k0 + 9) * B_LD + nn]) << 16);
            bl[0] = (uint32_t)__bfloat16_as_ushort(pBl[k0 * B_LD + nn]) |
                    ((uint32_t)__bfloat16_as_ushort(pBl[(k0 + 1) * B_LD + nn]) << 16);
            bl[1] = (uint32_t)__bfloat16_as_ushort(pBl[(k0 + 8) * B_LD + nn]) |
                    ((uint32_t)__bfloat16_as_ushort(pBl[(k0 + 9) * B_LD + nn]) << 16);
#pragma unroll
            for (int i = 0; i < 4; ++i) {
                MMA_BF16(acc[i][j], fah[i], bh);
                MMA_BF16(acc[i][j], fah[i], bl);
                MMA_BF16(acc[i][j], fal[i], bh);
            }
        }
        __syncthreads();
        if (c + 1 < NC) {
            store_smem((c + 1) & 1);
            __syncthreads();
        }
    }

    // ---- epilogue: direct from accumulator regs (PTX ISA D mapping) --------
    // d0:(g,2t) d1:(g,2t+1) d2:(g+8,2t) d3:(g+8,2t+1)
#pragma unroll
    for (int j = 0; j < 4; ++j) {
        int coll = n_base + j * 8 + tid4 * 2;
        float b0 = bias_e[coll];
        float b1 = bias_e[coll + 1];
        int gcol = n0 + coll;
#pragma unroll
        for (int i = 0; i < 4; ++i) {
            int row0 = r0 + m_base + i * 16 + g4;
            int row1 = row0 + 8;
            float v0 = acc[i][j][0] + b0;
            float v1 = acc[i][j][1] + b1;
            float v2 = acc[i][j][2] + b0;
            float v3 = acc[i][j][3] + b1;
            if (IS_GEMM1) {
                v0 = fmaxf(v0, 0.f); v1 = fmaxf(v1, 0.f);
                v2 = fmaxf(v2, 0.f); v3 = fmaxf(v3, 0.f);
            }
            if (row0 < seg_end) {
                float2 p; p.x = v0; p.y = v1;
                *(float2*)(Out + (size_t)row0 * NTOT + gcol) = p;
            }
            if (row1 < seg_end) {
                float2 p; p.x = v2; p.y = v3;
                *(float2*)(Out + (size_t)row1 * NTOT + gcol) = p;
            }
        }
    }
}

// ---------------- combine ----------------------------------------------------
__global__ void combine_kernel(float* __restrict__ y) {
    const int QD = ND / 4;
    int tid = blockIdx.x * blockDim.x + threadIdx.x;
    if (tid >= NB * QD) return;
    int b = tid / QD;
    int q = tid - b * QD;
    int p0 = g_pairpos[b * 2 + 0];
    int p1 = g_pairpos[b * 2 + 1];
    float w0 = g_wts[b * 2 + 0];
    float w1 = g_wts[b * 2 + 1];
    float4 o0 = ((const float4*)(g_outp + (size_t)p0 * ND))[q];
    float4 o1 = ((const float4*)(g_outp + (size_t)p1 * ND))[q];
    float4 r;
    r.x = w0 * o0.x + w1 * o1.x;
    r.y = w0 * o0.y + w1 * o1.y;
    r.z = w0 * o0.z + w1 * o1.z;
    r.w = w0 * o0.w + w1 * o1.w;
    ((float4*)y)[tid] = r;
}

// ---------------- launch ------------------------------------------------------
extern "C" void kernel_launch(void* const* d_in, const int* in_sizes, int n_in,
                              void* d_out, int out_size) {
    const float* x  = (const float*)d_in[0];
    const float* Wg = (const float*)d_in[1];
    const float* bg = (const float*)d_in[2];
    const float* W1 = (const float*)d_in[3];
    const float* b1 = (const float*)d_in[4];
    const float* W2 = (const float*)d_in[5];
    const float* b2 = (const float*)d_in[6];
    float* y = (float*)d_out;

    init_kernel<<<1, 32>>>();
    gating_kernel<<<(NB * 32) / 256, 256>>>(x, Wg, bg);
    route_build_kernel<<<1, 1>>>();
    assign_kernel<<<(NB * 2) / 256, 256>>>();

    // GEMM1: relu(x[gather] @ W1[e] + b1[e]) -> g_h (bound in device code)
    {
        dim3 g(NH / BN, MAX_TILES);
        gemm_mma_kernel<ND, true><<<g, 256>>>(x, W1, b1, NH);
    }
    // GEMM2: g_h @ W2[e] + b2[e] -> g_outp (bound in device code)
    {
        dim3 g(ND / BN, MAX_TILES);
        gemm_mma_kernel<NH, false><<<g, 256>>>(x, W2, b2, ND);
    }

    combine_kernel<<<(NB * (ND / 4) + 255) / 256, 256>>>(y);
}

// round 11
// speedup vs baseline: 2.1544x; 1.0271x over previous
#include <cuda_runtime.h>
#include <cuda_bf16.h>
#include <cstdint>
#include <math.h>

#define NB 32768      // tokens
#define ND 768        // model dim
#define NH 3072       // hidden dim
#define NE 8          // experts
#define BM 128
#define BN 128
#define BK 16
#define MAX_TILES ((NB * 2) / BM + NE)   // 520
#define PAD_ROWS (MAX_TILES * BM)        // 66560

#define OP_LD 24      // smem row stride (elements): 16 data + 8 pad = 48B

// ---------------- scratch (device globals; referenced ONLY by name in device
// code — never passed as kernel arguments from host; that was the R3-R9 bug) --
__device__ __nv_bfloat16 g_ahi[(size_t)PAD_ROWS * ND];
__device__ __nv_bfloat16 g_alo[(size_t)PAD_ROWS * ND];
__device__ __nv_bfloat16 g_hhi[(size_t)PAD_ROWS * NH];
__device__ __nv_bfloat16 g_hlo[(size_t)PAD_ROWS * NH];
__device__ float         g_outp[(size_t)PAD_ROWS * ND];
__device__ __nv_bfloat16 g_w1t_hi[(size_t)NE * NH * ND];  // [e][n][k]
__device__ __nv_bfloat16 g_w1t_lo[(size_t)NE * NH * ND];
__device__ __nv_bfloat16 g_w2t_hi[(size_t)NE * ND * NH];  // [e][n][k]
__device__ __nv_bfloat16 g_w2t_lo[(size_t)NE * ND * NH];
__device__ int   g_pair_token[PAD_ROWS];
__device__ int   g_pairpos[NB * 2];
__device__ float g_wts[NB * 2];
__device__ int   g_eidx[NB * 2];
__device__ int   g_counts[NE];
__device__ int   g_cursor[NE];
__device__ int   g_offsets[NE];
__device__ int   g_tile_expert[MAX_TILES];
__device__ int   g_tile_segend[MAX_TILES];

// ---------------- PTX helpers ------------------------------------------------
__device__ __forceinline__ uint32_t smem_to_u32(const void* p) {
    uint32_t a;
    asm("{ .reg .u64 t; cvta.to.shared.u64 t, %1; cvt.u32.u64 %0, t; }"
        : "=r"(a) : "l"(p));
    return a;
}
__device__ __forceinline__ void cp_async16(uint32_t smem, const void* g) {
    asm volatile("cp.async.cg.shared.global [%0], [%1], 16;" :: "r"(smem), "l"(g));
}
#define CP_COMMIT() asm volatile("cp.async.commit_group;" ::: "memory")
#define CP_WAIT(n)  asm volatile("cp.async.wait_group %0;" :: "n"(n) : "memory")

#define MMA_BF16(d, a, b) \
    asm volatile("mma.sync.aligned.m16n8k16.row.col.f32.bf16.bf16.f32 " \
        "{%0,%1,%2,%3}, {%4,%5,%6,%7}, {%8,%9}, {%0,%1,%2,%3};" \
        : "+f"((d)[0]), "+f"((d)[1]), "+f"((d)[2]), "+f"((d)[3]) \
        : "r"((a)[0]), "r"((a)[1]), "r"((a)[2]), "r"((a)[3]), \
          "r"((b)[0]), "r"((b)[1]))

// ---------------- init / gating / routing (proven) ---------------------------
__global__ void init_kernel() {
    if (threadIdx.x < NE) g_counts[threadIdx.x] = 0;
}

__global__ void gating_kernel(const float* __restrict__ x,
                              const float* __restrict__ Wg,
                              const float* __restrict__ bg) {
    int warp = (blockIdx.x * blockDim.x + threadIdx.x) >> 5;
    int lane = threadIdx.x & 31;
    if (warp >= NB) return;
    const float* xr = x + (size_t)warp * ND;
    float acc[8];
#pragma unroll
    for (int i = 0; i < 8; ++i) acc[i] = 0.f;
#pragma unroll 4
    for (int j = 0; j < ND / 32; ++j) {
        int d = j * 32 + lane;
        float xv = xr[d];
        const float* wr = Wg + (size_t)d * NE;
        float4 w0 = *(const float4*)(wr);
        float4 w1 = *(const float4*)(wr + 4);
        acc[0] += xv * w0.x; acc[1] += xv * w0.y;
        acc[2] += xv * w0.z; acc[3] += xv * w0.w;
        acc[4] += xv * w1.x; acc[5] += xv * w1.y;
        acc[6] += xv * w1.z; acc[7] += xv * w1.w;
    }
#pragma unroll
    for (int i = 0; i < 8; ++i)
#pragma unroll
        for (int off = 16; off > 0; off >>= 1)
            acc[i] += __shfl_xor_sync(0xFFFFFFFFu, acc[i], off);
    if (lane == 0) {
        float l[8];
#pragma unroll
        for (int i = 0; i < 8; ++i) l[i] = acc[i] + bg[i];
        int e0 = 0; float v0 = l[0];
#pragma unroll
        for (int i = 1; i < 8; ++i)
            if (l[i] > v0) { v0 = l[i]; e0 = i; }
        int e1 = -1; float v1 = -1e30f;
#pragma unroll
        for (int i = 0; i < 8; ++i)
            if (i != e0 && l[i] > v1) { v1 = l[i]; e1 = i; }
        float t  = expf(v1 - v0);
        float w0 = 1.f / (1.f + t);
        float w1 = t / (1.f + t);
        g_eidx[warp * 2 + 0] = e0;
        g_eidx[warp * 2 + 1] = e1;
        g_wts[warp * 2 + 0]  = w0;
        g_wts[warp * 2 + 1]  = w1;
        atomicAdd(&g_counts[e0], 1);
        atomicAdd(&g_counts[e1], 1);
    }
}

__global__ void route_build_kernel() {
    if (threadIdx.x == 0 && blockIdx.x == 0) {
        int off = 0, tile = 0;
        for (int e = 0; e < NE; ++e) {
            g_offsets[e] = off;
            g_cursor[e]  = 0;
            int c  = g_counts[e];
            int nt = (c + BM - 1) / BM;
            for (int i = 0; i < nt; ++i) {
                g_tile_expert[tile] = e;
                g_tile_segend[tile] = off + c;
                ++tile;
            }
            off += nt * BM;
        }
        for (; tile < MAX_TILES; ++tile) { g_tile_expert[tile] = -1; g_tile_segend[tile] = 0; }
    }
}

__global__ void assign_kernel() {
    int tid = blockIdx.x * blockDim.x + threadIdx.x;
    if (tid >= NB * 2) return;
    int b = tid >> 1;
    int e = g_eidx[tid];
    int pos = g_offsets[e] + atomicAdd(&g_cursor[e], 1);
    g_pair_token[pos] = b;
    g_pairpos[tid]    = pos;
}

// ---------------- gather x -> bf16 hi/lo pair rows ---------------------------
__global__ void gather_split_kernel(const float* __restrict__ x) {
    const int PER_ROW = ND / 8;
    int idx = blockIdx.x * blockDim.x + threadIdx.x;
    if (idx >= PAD_ROWS * PER_ROW) return;
    int r = idx / PER_ROW;
    int j = idx - r * PER_ROW;
    int rt = r >> 7;
    int tokv = -1;
    if (g_tile_expert[rt] >= 0 && r < g_tile_segend[rt]) tokv = g_pair_token[r];

    ushort hi[8], lo[8];
    if (tokv >= 0) {
        const float* xp = x + (size_t)tokv * ND + j * 8;
        float4 a = *(const float4*)xp;
        float4 b = *(const float4*)(xp + 4);
        float v[8] = {a.x, a.y, a.z, a.w, b.x, b.y, b.z, b.w};
#pragma unroll
        for (int i = 0; i < 8; ++i) {
            __nv_bfloat16 h = __float2bfloat16(v[i]);
            __nv_bfloat16 l = __float2bfloat16(v[i] - __bfloat162float(h));
            hi[i] = __bfloat16_as_ushort(h);
            lo[i] = __bfloat16_as_ushort(l);
        }
    } else {
#pragma unroll
        for (int i = 0; i < 8; ++i) { hi[i] = 0; lo[i] = 0; }
    }
    size_t o = (size_t)r * ND + j * 8;
    *(uint4*)(g_ahi + o) = *(uint4*)hi;
    *(uint4*)(g_alo + o) = *(uint4*)lo;
}

// ---------------- weight transpose+convert: W[e][K][N] -> [e][N][K] bf16 -----
template<bool IS_W1>
__global__ void wconv_kernel(const float* __restrict__ W, int K, int N) {
    __shared__ float tile[32][33];
    __nv_bfloat16* oh = IS_W1 ? g_w1t_hi : g_w2t_hi;
    __nv_bfloat16* ol = IS_W1 ? g_w1t_lo : g_w2t_lo;
    int e = blockIdx.z;
    const float* Win = W + (size_t)e * K * N;
    __nv_bfloat16* ohe = oh + (size_t)e * K * N;
    __nv_bfloat16* ole = ol + (size_t)e * K * N;
    int n0 = blockIdx.x * 32, k0 = blockIdx.y * 32;
    int tx = threadIdx.x, ty = threadIdx.y;
#pragma unroll
    for (int j = 0; j < 4; ++j)
        tile[ty + j * 8][tx] = Win[(size_t)(k0 + ty + j * 8) * N + n0 + tx];
    __syncthreads();
#pragma unroll
    for (int j = 0; j < 4; ++j) {
        float v = tile[tx][ty + j * 8];
        size_t o = (size_t)(n0 + ty + j * 8) * K + k0 + tx;
        __nv_bfloat16 h = __float2bfloat16(v);
        ohe[o] = h;
        ole[o] = __float2bfloat16(v - __bfloat162float(h));
    }
}

// ---------------- lean HMMA GEMM: cp.async + LDS + MMA only ------------------
// 256 threads = 8 warps 2(m) x 4(n); warp tile 64x32.
// A smem [m][k] hi/lo; B smem [n][k] hi/lo (both OP_LD stride, bf16, preconverted).
// All fragments = aligned 32-bit LDS (proven R10 k-pair construction).
// 3 products: Ah*Bh + Ah*Bl + Al*Bh, fp32 accumulate.
template<int KTOT, bool IS_GEMM1>
__global__ __launch_bounds__(256) void gemm_mma_kernel(
    const float* __restrict__ bias_all,  // b1 or b2 (harness pointer)
    int NTOT) {

    __shared__ __nv_bfloat16 sAh[2][BM * OP_LD];
    __shared__ __nv_bfloat16 sAl[2][BM * OP_LD];
    __shared__ __nv_bfloat16 sBh[2][BN * OP_LD];
    __shared__ __nv_bfloat16 sBl[2][BN * OP_LD];

    // device-side binding of all scratch (never passed from host)
    const __nv_bfloat16* Ahi = IS_GEMM1 ? g_ahi : g_hhi;
    const __nv_bfloat16* Alo = IS_GEMM1 ? g_alo : g_hlo;
    const __nv_bfloat16* Bhi = IS_GEMM1 ? g_w1t_hi : g_w2t_hi;
    const __nv_bfloat16* Blo = IS_GEMM1 ? g_w1t_lo : g_w2t_lo;

    int rt = blockIdx.y;
    int e  = g_tile_expert[rt];
    if (e < 0) return;
    int seg_end = g_tile_segend[rt];
    int r0 = rt * BM;
    int n0 = blockIdx.x * BN;

    int t = threadIdx.x;
    int lane = t & 31;
    int warp = t >> 5;
    int m_base = (warp & 1) * 64;
    int n_base = (warp >> 1) * 32;
    int g4   = lane >> 2;   // 0..7
    int tid4 = lane & 3;    // 0..3

    // ---- cp.async loader mapping: thread t -> row t>>1, 16B half t&1 --------
    int row  = t >> 1;
    int half = t & 1;
    const __nv_bfloat16* aPh = Ahi + (size_t)(r0 + row) * KTOT + half * 8;
    const __nv_bfloat16* aPl = Alo + (size_t)(r0 + row) * KTOT + half * 8;
    const __nv_bfloat16* bPh = Bhi + ((size_t)e * NTOT + n0 + row) * KTOT + half * 8;
    const __nv_bfloat16* bPl = Blo + ((size_t)e * NTOT + n0 + row) * KTOT + half * 8;
    uint32_t so = (uint32_t)((row * OP_LD + half * 8) * 2);   // 16B-aligned
    uint32_t uAh = smem_to_u32(sAh) + so;
    uint32_t uAl = smem_to_u32(sAl) + so;
    uint32_t uBh = smem_to_u32(sBh) + so;
    uint32_t uBl = smem_to_u32(sBl) + so;
    const uint32_t stage_b = BM * OP_LD * 2;   // bytes per stage

    auto issue = [&](int c, int s) {
        uint32_t off = (uint32_t)s * stage_b;
        size_t go = (size_t)c * BK;
        cp_async16(uAh + off, aPh + go);
        cp_async16(uAl + off, aPl + go);
        cp_async16(uBh + off, bPh + go);
        cp_async16(uBl + off, bPl + go);
    };

    const float* bias_e = bias_all + (size_t)e * NTOT + n0;

    float acc[4][4][4];
#pragma unroll
    for (int i = 0; i < 4; ++i)
#pragma unroll
        for (int j = 0; j < 4; ++j)
#pragma unroll
            for (int q = 0; q < 4; ++q) acc[i][j][q] = 0.f;

    const int NC = KTOT / BK;

    issue(0, 0); CP_COMMIT();

    for (int c = 0; c < NC; ++c) {
        int s = c & 1;
        if (c + 1 < NC) {
            issue(c + 1, s ^ 1); CP_COMMIT();
            CP_WAIT(1);
        } else {
            CP_WAIT(0);
        }
        __syncthreads();

        const __nv_bfloat16* pAh = sAh[s];
        const __nv_bfloat16* pAl = sAl[s];
        const __nv_bfloat16* pBh = sBh[s];
        const __nv_bfloat16* pBl = sBl[s];

        // A fragments: a0:(g,2t) a1:(g+8,2t) a2:(g,2t+8) a3:(g+8,2t+8)
        uint32_t fah[4][4], fal[4][4];
#pragma unroll
        for (int i = 0; i < 4; ++i) {
            int rlo = (m_base + i * 16 + g4) * OP_LD + tid4 * 2;
            int rhi = rlo + 8 * OP_LD;
            fah[i][0] = *(const uint32_t*)&pAh[rlo];
            fah[i][1] = *(const uint32_t*)&pAh[rhi];
            fah[i][2] = *(const uint32_t*)&pAh[rlo + 8];
            fah[i][3] = *(const uint32_t*)&pAh[rhi + 8];
            fal[i][0] = *(const uint32_t*)&pAl[rlo];
            fal[i][1] = *(const uint32_t*)&pAl[rhi];
            fal[i][2] = *(const uint32_t*)&pAl[rlo + 8];
            fal[i][3] = *(const uint32_t*)&pAl[rhi + 8];
        }
        // B fragments from [n][k] smem: b0={B[2t][n],B[2t+1][n]} = one 32-bit LDS
#pragma unroll
        for (int j = 0; j < 4; ++j) {
            int nrow = (n_base + j * 8 + g4) * OP_LD + tid4 * 2;
            uint32_t bh[2], bl[2];
            bh[0] = *(const uint32_t*)&pBh[nrow];
            bh[1] = *(const uint32_t*)&pBh[nrow + 8];
            bl[0] = *(const uint32_t*)&pBl[nrow];
            bl[1] = *(const uint32_t*)&pBl[nrow + 8];
#pragma unroll
            for (int i = 0; i < 4; ++i) {
                MMA_BF16(acc[i][j], fah[i], bh);
                MMA_BF16(acc[i][j], fah[i], bl);
                MMA_BF16(acc[i][j], fal[i], bh);
            }
        }
        __syncthreads();
    }

    // ---- epilogue: direct from accumulator regs -----------------------------
    // d0:(g,2t) d1:(g,2t+1) d2:(g+8,2t) d3:(g+8,2t+1)
#pragma unroll
    for (int j = 0; j < 4; ++j) {
        int coll = n_base + j * 8 + tid4 * 2;
        float b0 = bias_e[coll];
        float b1 = bias_e[coll + 1];
        int gcol = n0 + coll;
#pragma unroll
        for (int i = 0; i < 4; ++i) {
            int row0 = r0 + m_base + i * 16 + g4;
            int row1 = row0 + 8;
            float v0 = acc[i][j][0] + b0;
            float v1 = acc[i][j][1] + b1;
            float v2 = acc[i][j][2] + b0;
            float v3 = acc[i][j][3] + b1;
            if (IS_GEMM1) {
                v0 = fmaxf(v0, 0.f); v1 = fmaxf(v1, 0.f);
                v2 = fmaxf(v2, 0.f); v3 = fmaxf(v3, 0.f);
                // write h as bf16 hi/lo pairs (packed u32)
                if (row0 < seg_end) {
                    __nv_bfloat16 h0 = __float2bfloat16(v0);
                    __nv_bfloat16 h1 = __float2bfloat16(v1);
                    __nv_bfloat16 l0 = __float2bfloat16(v0 - __bfloat162float(h0));
                    __nv_bfloat16 l1 = __float2bfloat16(v1 - __bfloat162float(h1));
                    uint32_t ph = (uint32_t)__bfloat16_as_ushort(h0) |
                                  ((uint32_t)__bfloat16_as_ushort(h1) << 16);
                    uint32_t pl = (uint32_t)__bfloat16_as_ushort(l0) |
                                  ((uint32_t)__bfloat16_as_ushort(l1) << 16);
                    *(uint32_t*)(g_hhi + (size_t)row0 * NH + gcol) = ph;
                    *(uint32_t*)(g_hlo + (size_t)row0 * NH + gcol) = pl;
                }
                if (row1 < seg_end) {
                    __nv_bfloat16 h0 = __float2bfloat16(v2);
                    __nv_bfloat16 h1 = __float2bfloat16(v3);
                    __nv_bfloat16 l0 = __float2bfloat16(v2 - __bfloat162float(h0));
                    __nv_bfloat16 l1 = __float2bfloat16(v3 - __bfloat162float(h1));
                    uint32_t ph = (uint32_t)__bfloat16_as_ushort(h0) |
                                  ((uint32_t)__bfloat16_as_ushort(h1) << 16);
                    uint32_t pl = (uint32_t)__bfloat16_as_ushort(l0) |
                                  ((uint32_t)__bfloat16_as_ushort(l1) << 16);
                    *(uint32_t*)(g_hhi + (size_t)row1 * NH + gcol) = ph;
                    *(uint32_t*)(g_hlo + (size_t)row1 * NH + gcol) = pl;
                }
            } else {
                if (row0 < seg_end) {
                    float2 p; p.x = v0; p.y = v1;
                    *(float2*)(g_outp + (size_t)row0 * ND + gcol) = p;
                }
                if (row1 < seg_end) {
                    float2 p; p.x = v2; p.y = v3;
                    *(float2*)(g_outp + (size_t)row1 * ND + gcol) = p;
                }
            }
        }
    }
}

// ---------------- combine ----------------------------------------------------
__global__ void combine_kernel(float* __restrict__ y) {
    const int QD = ND / 4;
    int tid = blockIdx.x * blockDim.x + threadIdx.x;
    if (tid >= NB * QD) return;
    int b = tid / QD;
    int q = tid - b * QD;
    int p0 = g_pairpos[b * 2 + 0];
    int p1 = g_pairpos[b * 2 + 1];
    float w0 = g_wts[b * 2 + 0];
    float w1 = g_wts[b * 2 + 1];
    float4 o0 = ((const float4*)(g_outp + (size_t)p0 * ND))[q];
    float4 o1 = ((const float4*)(g_outp + (size_t)p1 * ND))[q];
    float4 r;
    r.x = w0 * o0.x + w1 * o1.x;
    r.y = w0 * o0.y + w1 * o1.y;
    r.z = w0 * o0.z + w1 * o1.z;
    r.w = w0 * o0.w + w1 * o1.w;
    ((float4*)y)[tid] = r;
}

// ---------------- launch ------------------------------------------------------
extern "C" void kernel_launch(void* const* d_in, const int* in_sizes, int n_in,
                              void* d_out, int out_size) {
    const float* x  = (const float*)d_in[0];
    const float* Wg = (const float*)d_in[1];
    const float* bg = (const float*)d_in[2];
    const float* W1 = (const float*)d_in[3];
    const float* b1 = (const float*)d_in[4];
    const float* W2 = (const float*)d_in[5];
    const float* b2 = (const float*)d_in[6];
    float* y = (float*)d_out;

    init_kernel<<<1, 32>>>();
    gating_kernel<<<(NB * 32) / 256, 256>>>(x, Wg, bg);
    route_build_kernel<<<1, 1>>>();
    assign_kernel<<<(NB * 2) / 256, 256>>>();

    // one-time conversions
    {
        dim3 g(NH / 32, ND / 32, NE);
        wconv_kernel<true><<<g, dim3(32, 8)>>>(W1, ND, NH);
    }
    {
        dim3 g(ND / 32, NH / 32, NE);
        wconv_kernel<false><<<g, dim3(32, 8)>>>(W2, NH, ND);
    }
    {
        int total = PAD_ROWS * (ND / 8);
        gather_split_kernel<<<(total + 255) / 256, 256>>>(x);
    }

    // GEMM1: relu(x[gather] @ W1[e] + b1[e]) -> g_hhi/g_hlo
    {
        dim3 g(NH / BN, MAX_TILES);
        gemm_mma_kernel<ND, true><<<g, 256>>>(b1, NH);
    }
    // GEMM2: h @ W2[e] + b2[e] -> g_outp
    {
        dim3 g(ND / BN, MAX_TILES);
        gemm_mma_kernel<NH, false><<<g, 256>>>(b2, ND);
    }

    combine_kernel<<<(NB * (ND / 4) + 255) / 256, 256>>>(y);
}

// round 12
// speedup vs baseline: 2.1908x; 1.0169x over previous
#include <cuda_runtime.h>
#include <cuda_bf16.h>
#include <cstdint>
#include <math.h>

#define NB 32768      // tokens
#define ND 768        // model dim
#define NH 3072       // hidden dim
#define NE 8          // experts
#define BM 128
#define BN 128
#define BK 16
#define MAX_TILES ((NB * 2) / BM + NE)   // 520
#define PAD_ROWS (MAX_TILES * BM)        // 66560

#define OP_LD 24      // smem row stride (elements): 16 data + 8 pad = 48B

// ---------------- scratch (device globals; referenced ONLY by name in device
// code — never passed as kernel arguments from host) --------------------------
__device__ __nv_bfloat16 g_ahi[(size_t)PAD_ROWS * ND];
__device__ __nv_bfloat16 g_alo[(size_t)PAD_ROWS * ND];
__device__ __nv_bfloat16 g_hhi[(size_t)PAD_ROWS * NH];
__device__ __nv_bfloat16 g_hlo[(size_t)PAD_ROWS * NH];
__device__ float         g_outp[(size_t)PAD_ROWS * ND];
__device__ __nv_bfloat16 g_w1t_hi[(size_t)NE * NH * ND];  // [e][n][k]
__device__ __nv_bfloat16 g_w1t_lo[(size_t)NE * NH * ND];
__device__ __nv_bfloat16 g_w2t_hi[(size_t)NE * ND * NH];  // [e][n][k]
__device__ __nv_bfloat16 g_w2t_lo[(size_t)NE * ND * NH];
__device__ int   g_pair_token[PAD_ROWS];
__device__ int   g_pairpos[NB * 2];
__device__ float g_wts[NB * 2];
__device__ int   g_eidx[NB * 2];
__device__ int   g_counts[NE];
__device__ int   g_cursor[NE];
__device__ int   g_offsets[NE];
__device__ int   g_tile_expert[MAX_TILES];
__device__ int   g_tile_segend[MAX_TILES];

// ---------------- PTX helpers ------------------------------------------------
__device__ __forceinline__ uint32_t smem_to_u32(const void* p) {
    uint32_t a;
    asm("{ .reg .u64 t; cvta.to.shared.u64 t, %1; cvt.u32.u64 %0, t; }"
        : "=r"(a) : "l"(p));
    return a;
}
__device__ __forceinline__ void cp_async16(uint32_t smem, const void* g) {
    asm volatile("cp.async.cg.shared.global [%0], [%1], 16;" :: "r"(smem), "l"(g));
}
#define CP_COMMIT() asm volatile("cp.async.commit_group;" ::: "memory")
#define CP_WAIT(n)  asm volatile("cp.async.wait_group %0;" :: "n"(n) : "memory")

#define MMA_BF16(d, a, b) \
    asm volatile("mma.sync.aligned.m16n8k16.row.col.f32.bf16.bf16.f32 " \
        "{%0,%1,%2,%3}, {%4,%5,%6,%7}, {%8,%9}, {%0,%1,%2,%3};" \
        : "+f"((d)[0]), "+f"((d)[1]), "+f"((d)[2]), "+f"((d)[3]) \
        : "r"((a)[0]), "r"((a)[1]), "r"((a)[2]), "r"((a)[3]), \
          "r"((b)[0]), "r"((b)[1]))

// ---------------- init / gating / routing (proven) ---------------------------
__global__ void init_kernel() {
    if (threadIdx.x < NE) g_counts[threadIdx.x] = 0;
}

__global__ void gating_kernel(const float* __restrict__ x,
                              const float* __restrict__ Wg,
                              const float* __restrict__ bg) {
    int warp = (blockIdx.x * blockDim.x + threadIdx.x) >> 5;
    int lane = threadIdx.x & 31;
    if (warp >= NB) return;
    const float* xr = x + (size_t)warp * ND;
    float acc[8];
#pragma unroll
    for (int i = 0; i < 8; ++i) acc[i] = 0.f;
#pragma unroll 4
    for (int j = 0; j < ND / 32; ++j) {
        int d = j * 32 + lane;
        float xv = xr[d];
        const float* wr = Wg + (size_t)d * NE;
        float4 w0 = *(const float4*)(wr);
        float4 w1 = *(const float4*)(wr + 4);
        acc[0] += xv * w0.x; acc[1] += xv * w0.y;
        acc[2] += xv * w0.z; acc[3] += xv * w0.w;
        acc[4] += xv * w1.x; acc[5] += xv * w1.y;
        acc[6] += xv * w1.z; acc[7] += xv * w1.w;
    }
#pragma unroll
    for (int i = 0; i < 8; ++i)
#pragma unroll
        for (int off = 16; off > 0; off >>= 1)
            acc[i] += __shfl_xor_sync(0xFFFFFFFFu, acc[i], off);
    if (lane == 0) {
        float l[8];
#pragma unroll
        for (int i = 0; i < 8; ++i) l[i] = acc[i] + bg[i];
        int e0 = 0; float v0 = l[0];
#pragma unroll
        for (int i = 1; i < 8; ++i)
            if (l[i] > v0) { v0 = l[i]; e0 = i; }
        int e1 = -1; float v1 = -1e30f;
#pragma unroll
        for (int i = 0; i < 8; ++i)
            if (i != e0 && l[i] > v1) { v1 = l[i]; e1 = i; }
        float t  = expf(v1 - v0);
        float w0 = 1.f / (1.f + t);
        float w1 = t / (1.f + t);
        g_eidx[warp * 2 + 0] = e0;
        g_eidx[warp * 2 + 1] = e1;
        g_wts[warp * 2 + 0]  = w0;
        g_wts[warp * 2 + 1]  = w1;
        atomicAdd(&g_counts[e0], 1);
        atomicAdd(&g_counts[e1], 1);
    }
}

__global__ void route_build_kernel() {
    if (threadIdx.x == 0 && blockIdx.x == 0) {
        int off = 0, tile = 0;
        for (int e = 0; e < NE; ++e) {
            g_offsets[e] = off;
            g_cursor[e]  = 0;
            int c  = g_counts[e];
            int nt = (c + BM - 1) / BM;
            for (int i = 0; i < nt; ++i) {
                g_tile_expert[tile] = e;
                g_tile_segend[tile] = off + c;
                ++tile;
            }
            off += nt * BM;
        }
        for (; tile < MAX_TILES; ++tile) { g_tile_expert[tile] = -1; g_tile_segend[tile] = 0; }
    }
}

__global__ void assign_kernel() {
    int tid = blockIdx.x * blockDim.x + threadIdx.x;
    if (tid >= NB * 2) return;
    int b = tid >> 1;
    int e = g_eidx[tid];
    int pos = g_offsets[e] + atomicAdd(&g_cursor[e], 1);
    g_pair_token[pos] = b;
    g_pairpos[tid]    = pos;
}

// ---------------- gather x -> bf16 hi/lo pair rows ---------------------------
__global__ void gather_split_kernel(const float* __restrict__ x) {
    const int PER_ROW = ND / 8;
    int idx = blockIdx.x * blockDim.x + threadIdx.x;
    if (idx >= PAD_ROWS * PER_ROW) return;
    int r = idx / PER_ROW;
    int j = idx - r * PER_ROW;
    int rt = r >> 7;
    int tokv = -1;
    if (g_tile_expert[rt] >= 0 && r < g_tile_segend[rt]) tokv = g_pair_token[r];

    ushort hi[8], lo[8];
    if (tokv >= 0) {
        const float* xp = x + (size_t)tokv * ND + j * 8;
        float4 a = *(const float4*)xp;
        float4 b = *(const float4*)(xp + 4);
        float v[8] = {a.x, a.y, a.z, a.w, b.x, b.y, b.z, b.w};
#pragma unroll
        for (int i = 0; i < 8; ++i) {
            __nv_bfloat16 h = __float2bfloat16(v[i]);
            __nv_bfloat16 l = __float2bfloat16(v[i] - __bfloat162float(h));
            hi[i] = __bfloat16_as_ushort(h);
            lo[i] = __bfloat16_as_ushort(l);
        }
    } else {
#pragma unroll
        for (int i = 0; i < 8; ++i) { hi[i] = 0; lo[i] = 0; }
    }
    size_t o = (size_t)r * ND + j * 8;
    *(uint4*)(g_ahi + o) = *(uint4*)hi;
    *(uint4*)(g_alo + o) = *(uint4*)lo;
}

// ---------------- weight transpose+convert: W[e][K][N] -> [e][N][K] bf16 -----
template<bool IS_W1>
__global__ void wconv_kernel(const float* __restrict__ W, int K, int N) {
    __shared__ float tile[32][33];
    __nv_bfloat16* oh = IS_W1 ? g_w1t_hi : g_w2t_hi;
    __nv_bfloat16* ol = IS_W1 ? g_w1t_lo : g_w2t_lo;
    int e = blockIdx.z;
    const float* Win = W + (size_t)e * K * N;
    __nv_bfloat16* ohe = oh + (size_t)e * K * N;
    __nv_bfloat16* ole = ol + (size_t)e * K * N;
    int n0 = blockIdx.x * 32, k0 = blockIdx.y * 32;
    int tx = threadIdx.x, ty = threadIdx.y;
#pragma unroll
    for (int j = 0; j < 4; ++j)
        tile[ty + j * 8][tx] = Win[(size_t)(k0 + ty + j * 8) * N + n0 + tx];
    __syncthreads();
#pragma unroll
    for (int j = 0; j < 4; ++j) {
        float v = tile[tx][ty + j * 8];
        size_t o = (size_t)(n0 + ty + j * 8) * K + k0 + tx;
        __nv_bfloat16 h = __float2bfloat16(v);
        ohe[o] = h;
        ole[o] = __float2bfloat16(v - __bfloat162float(h));
    }
}

// ---------------- lean HMMA GEMM (occupancy 2, chain-broken order) -----------
// 256 threads = 8 warps 2(m) x 4(n); warp tile 64x32.
// A smem [m][k] hi/lo; B smem [n][k] hi/lo (OP_LD stride, preconverted bf16).
// B frags preloaded for all j (16 regs); A frags loaded per i (8 live regs).
// MMA order per i: hh(j0..j3), hl(j0..j3), lh(j0..j3) — dependent MMAs to one
// accumulator are 4 apart; per-acc product order unchanged (bitwise identical).
template<int KTOT, bool IS_GEMM1>
__global__ __launch_bounds__(256, 2) void gemm_mma_kernel(
    const float* __restrict__ bias_all,  // b1 or b2 (harness pointer)
    int NTOT) {

    __shared__ __nv_bfloat16 sAh[2][BM * OP_LD];
    __shared__ __nv_bfloat16 sAl[2][BM * OP_LD];
    __shared__ __nv_bfloat16 sBh[2][BN * OP_LD];
    __shared__ __nv_bfloat16 sBl[2][BN * OP_LD];

    const __nv_bfloat16* Ahi = IS_GEMM1 ? g_ahi : g_hhi;
    const __nv_bfloat16* Alo = IS_GEMM1 ? g_alo : g_hlo;
    const __nv_bfloat16* Bhi = IS_GEMM1 ? g_w1t_hi : g_w2t_hi;
    const __nv_bfloat16* Blo = IS_GEMM1 ? g_w1t_lo : g_w2t_lo;

    int rt = blockIdx.y;
    int e  = g_tile_expert[rt];
    if (e < 0) return;
    int seg_end = g_tile_segend[rt];
    int r0 = rt * BM;
    int n0 = blockIdx.x * BN;

    int t = threadIdx.x;
    int lane = t & 31;
    int warp = t >> 5;
    int m_base = (warp & 1) * 64;
    int n_base = (warp >> 1) * 32;
    int g4   = lane >> 2;   // 0..7
    int tid4 = lane & 3;    // 0..3

    // ---- cp.async loader mapping: thread t -> row t>>1, 16B half t&1 --------
    int row  = t >> 1;
    int half = t & 1;
    const __nv_bfloat16* aPh = Ahi + (size_t)(r0 + row) * KTOT + half * 8;
    const __nv_bfloat16* aPl = Alo + (size_t)(r0 + row) * KTOT + half * 8;
    const __nv_bfloat16* bPh = Bhi + ((size_t)e * NTOT + n0 + row) * KTOT + half * 8;
    const __nv_bfloat16* bPl = Blo + ((size_t)e * NTOT + n0 + row) * KTOT + half * 8;
    uint32_t so = (uint32_t)((row * OP_LD + half * 8) * 2);
    uint32_t uAh = smem_to_u32(sAh) + so;
    uint32_t uAl = smem_to_u32(sAl) + so;
    uint32_t uBh = smem_to_u32(sBh) + so;
    uint32_t uBl = smem_to_u32(sBl) + so;
    const uint32_t stage_b = BM * OP_LD * 2;

    auto issue = [&](int c, int s) {
        uint32_t off = (uint32_t)s * stage_b;
        size_t go = (size_t)c * BK;
        cp_async16(uAh + off, aPh + go);
        cp_async16(uAl + off, aPl + go);
        cp_async16(uBh + off, bPh + go);
        cp_async16(uBl + off, bPl + go);
    };

    const float* bias_e = bias_all + (size_t)e * NTOT + n0;

    float acc[4][4][4];
#pragma unroll
    for (int i = 0; i < 4; ++i)
#pragma unroll
        for (int j = 0; j < 4; ++j)
#pragma unroll
            for (int q = 0; q < 4; ++q) acc[i][j][q] = 0.f;

    const int NC = KTOT / BK;

    issue(0, 0); CP_COMMIT();

    for (int c = 0; c < NC; ++c) {
        int s = c & 1;
        if (c + 1 < NC) {
            issue(c + 1, s ^ 1); CP_COMMIT();
            CP_WAIT(1);
        } else {
            CP_WAIT(0);
        }
        __syncthreads();

        const __nv_bfloat16* pAh = sAh[s];
        const __nv_bfloat16* pAl = sAl[s];
        const __nv_bfloat16* pBh = sBh[s];
        const __nv_bfloat16* pBl = sBl[s];

        // B fragments for all j (reused across i): one 32-bit LDS each
        uint32_t bh[4][2], bl[4][2];
#pragma unroll
        for (int j = 0; j < 4; ++j) {
            int nrow = (n_base + j * 8 + g4) * OP_LD + tid4 * 2;
            bh[j][0] = *(const uint32_t*)&pBh[nrow];
            bh[j][1] = *(const uint32_t*)&pBh[nrow + 8];
            bl[j][0] = *(const uint32_t*)&pBl[nrow];
            bl[j][1] = *(const uint32_t*)&pBl[nrow + 8];
        }

#pragma unroll
        for (int i = 0; i < 4; ++i) {
            // A fragments for this i only (8 live regs)
            uint32_t fah[4], fal[4];
            int rlo = (m_base + i * 16 + g4) * OP_LD + tid4 * 2;
            int rhi = rlo + 8 * OP_LD;
            fah[0] = *(const uint32_t*)&pAh[rlo];
            fah[1] = *(const uint32_t*)&pAh[rhi];
            fah[2] = *(const uint32_t*)&pAh[rlo + 8];
            fah[3] = *(const uint32_t*)&pAh[rhi + 8];
            fal[0] = *(const uint32_t*)&pAl[rlo];
            fal[1] = *(const uint32_t*)&pAl[rhi];
            fal[2] = *(const uint32_t*)&pAl[rlo + 8];
            fal[3] = *(const uint32_t*)&pAl[rhi + 8];
            // product-major: dependent MMAs to one acc are 4 apart
#pragma unroll
            for (int j = 0; j < 4; ++j) MMA_BF16(acc[i][j], fah, bh[j]);
#pragma unroll
            for (int j = 0; j < 4; ++j) MMA_BF16(acc[i][j], fah, bl[j]);
#pragma unroll
            for (int j = 0; j < 4; ++j) MMA_BF16(acc[i][j], fal, bh[j]);
        }
        __syncthreads();
    }

    // ---- epilogue: direct from accumulator regs -----------------------------
#pragma unroll
    for (int j = 0; j < 4; ++j) {
        int coll = n_base + j * 8 + tid4 * 2;
        float b0 = bias_e[coll];
        float b1 = bias_e[coll + 1];
        int gcol = n0 + coll;
#pragma unroll
        for (int i = 0; i < 4; ++i) {
            int row0 = r0 + m_base + i * 16 + g4;
            int row1 = row0 + 8;
            float v0 = acc[i][j][0] + b0;
            float v1 = acc[i][j][1] + b1;
            float v2 = acc[i][j][2] + b0;
            float v3 = acc[i][j][3] + b1;
            if (IS_GEMM1) {
                v0 = fmaxf(v0, 0.f); v1 = fmaxf(v1, 0.f);
                v2 = fmaxf(v2, 0.f); v3 = fmaxf(v3, 0.f);
                if (row0 < seg_end) {
                    __nv_bfloat16 h0 = __float2bfloat16(v0);
                    __nv_bfloat16 h1 = __float2bfloat16(v1);
                    __nv_bfloat16 l0 = __float2bfloat16(v0 - __bfloat162float(h0));
                    __nv_bfloat16 l1 = __float2bfloat16(v1 - __bfloat162float(h1));
                    uint32_t ph = (uint32_t)__bfloat16_as_ushort(h0) |
                                  ((uint32_t)__bfloat16_as_ushort(h1) << 16);
                    uint32_t pl = (uint32_t)__bfloat16_as_ushort(l0) |
                                  ((uint32_t)__bfloat16_as_ushort(l1) << 16);
                    *(uint32_t*)(g_hhi + (size_t)row0 * NH + gcol) = ph;
                    *(uint32_t*)(g_hlo + (size_t)row0 * NH + gcol) = pl;
                }
                if (row1 < seg_end) {
                    __nv_bfloat16 h0 = __float2bfloat16(v2);
                    __nv_bfloat16 h1 = __float2bfloat16(v3);
                    __nv_bfloat16 l0 = __float2bfloat16(v2 - __bfloat162float(h0));
                    __nv_bfloat16 l1 = __float2bfloat16(v3 - __bfloat162float(h1));
                    uint32_t ph = (uint32_t)__bfloat16_as_ushort(h0) |
                                  ((uint32_t)__bfloat16_as_ushort(h1) << 16);
                    uint32_t pl = (uint32_t)__bfloat16_as_ushort(l0) |
                                  ((uint32_t)__bfloat16_as_ushort(l1) << 16);
                    *(uint32_t*)(g_hhi + (size_t)row1 * NH + gcol) = ph;
                    *(uint32_t*)(g_hlo + (size_t)row1 * NH + gcol) = pl;
                }
            } else {
                if (row0 < seg_end) {
                    float2 p; p.x = v0; p.y = v1;
                    *(float2*)(g_outp + (size_t)row0 * ND + gcol) = p;
                }
                if (row1 < seg_end) {
                    float2 p; p.x = v2; p.y = v3;
                    *(float2*)(g_outp + (size_t)row1 * ND + gcol) = p;
                }
            }
        }
    }
}

// ---------------- combine ----------------------------------------------------
__global__ void combine_kernel(float* __restrict__ y) {
    const int QD = ND / 4;
    int tid = blockIdx.x * blockDim.x + threadIdx.x;
    if (tid >= NB * QD) return;
    int b = tid / QD;
    int q = tid - b * QD;
    int p0 = g_pairpos[b * 2 + 0];
    int p1 = g_pairpos[b * 2 + 1];
    float w0 = g_wts[b * 2 + 0];
    float w1 = g_wts[b * 2 + 1];
    float4 o0 = ((const float4*)(g_outp + (size_t)p0 * ND))[q];
    float4 o1 = ((const float4*)(g_outp + (size_t)p1 * ND))[q];
    float4 r;
    r.x = w0 * o0.x + w1 * o1.x;
    r.y = w0 * o0.y + w1 * o1.y;
    r.z = w0 * o0.z + w1 * o1.z;
    r.w = w0 * o0.w + w1 * o1.w;
    ((float4*)y)[tid] = r;
}

// ---------------- launch ------------------------------------------------------
extern "C" void kernel_launch(void* const* d_in, const int* in_sizes, int n_in,
                              void* d_out, int out_size) {
    const float* x  = (const float*)d_in[0];
    const float* Wg = (const float*)d_in[1];
    const float* bg = (const float*)d_in[2];
    const float* W1 = (const float*)d_in[3];
    const float* b1 = (const float*)d_in[4];
    const float* W2 = (const float*)d_in[5];
    const float* b2 = (const float*)d_in[6];
    float* y = (float*)d_out;

    init_kernel<<<1, 32>>>();
    gating_kernel<<<(NB * 32) / 256, 256>>>(x, Wg, bg);
    route_build_kernel<<<1, 1>>>();
    assign_kernel<<<(NB * 2) / 256, 256>>>();

    // one-time conversions
    {
        dim3 g(NH / 32, ND / 32, NE);
        wconv_kernel<true><<<g, dim3(32, 8)>>>(W1, ND, NH);
    }
    {
        dim3 g(ND / 32, NH / 32, NE);
        wconv_kernel<false><<<g, dim3(32, 8)>>>(W2, NH, ND);
    }
    {
        int total = PAD_ROWS * (ND / 8);
        gather_split_kernel<<<(total + 255) / 256, 256>>>(x);
    }

    // GEMM1: relu(x[gather] @ W1[e] + b1[e]) -> g_hhi/g_hlo
    {
        dim3 g(NH / BN, MAX_TILES);
        gemm_mma_kernel<ND, true><<<g, 256>>>(b1, NH);
    }
    // GEMM2: h @ W2[e] + b2[e] -> g_outp
    {
        dim3 g(ND / BN, MAX_TILES);
        gemm_mma_kernel<NH, false><<<g, 256>>>(b2, ND);
    }

    combine_kernel<<<(NB * (ND / 4) + 255) / 256, 256>>>(y);
}

// round 13
// speedup vs baseline: 3.0907x; 1.4108x over previous
#include <cuda_runtime.h>
#include <cuda_fp16.h>
#include <cstdint>
#include <math.h>

#define NB 32768      // tokens
#define ND 768        // model dim
#define NH 3072       // hidden dim
#define NE 8          // experts
#define BM 128
#define BN 128
#define BK 16
#define MAX_TILES ((NB * 2) / BM + NE)   // 520
#define PAD_ROWS (MAX_TILES * BM)        // 66560

#define OP_LD 24      // smem row stride (elements): 16 data + 8 pad = 48B

// ---------------- scratch (device globals; referenced ONLY by name in device
// code — never passed as kernel arguments from host) --------------------------
__device__ __half g_a16[(size_t)PAD_ROWS * ND];    // fp16(x) gathered pair rows
__device__ __half g_h16[(size_t)PAD_ROWS * NH];    // fp16(relu(h)) activations
__device__ float  g_outp[(size_t)PAD_ROWS * ND];   // per-pair expert outputs
__device__ __half g_w1t_hi[(size_t)NE * NH * ND];  // [e][n][k] fp16 hi
__device__ __half g_w1t_lo[(size_t)NE * NH * ND];  // [e][n][k] fp16 lo
__device__ __half g_w2t_hi[(size_t)NE * ND * NH];
__device__ __half g_w2t_lo[(size_t)NE * ND * NH];
__device__ int   g_pair_token[PAD_ROWS];
__device__ int   g_pairpos[NB * 2];
__device__ float g_wts[NB * 2];
__device__ int   g_eidx[NB * 2];
__device__ int   g_counts[NE];
__device__ int   g_cursor[NE];
__device__ int   g_offsets[NE];
__device__ int   g_tile_expert[MAX_TILES];
__device__ int   g_tile_segend[MAX_TILES];

// ---------------- PTX helpers ------------------------------------------------
__device__ __forceinline__ uint32_t smem_to_u32(const void* p) {
    uint32_t a;
    asm("{ .reg .u64 t; cvta.to.shared.u64 t, %1; cvt.u32.u64 %0, t; }"
        : "=r"(a) : "l"(p));
    return a;
}
__device__ __forceinline__ void cp_async16(uint32_t smem, const void* g) {
    asm volatile("cp.async.cg.shared.global [%0], [%1], 16;" :: "r"(smem), "l"(g));
}
#define CP_COMMIT() asm volatile("cp.async.commit_group;" ::: "memory")
#define CP_WAIT(n)  asm volatile("cp.async.wait_group %0;" :: "n"(n) : "memory")

#define MMA_F16(d, a, b) \
    asm volatile("mma.sync.aligned.m16n8k16.row.col.f32.f16.f16.f32 " \
        "{%0,%1,%2,%3}, {%4,%5,%6,%7}, {%8,%9}, {%0,%1,%2,%3};" \
        : "+f"((d)[0]), "+f"((d)[1]), "+f"((d)[2]), "+f"((d)[3]) \
        : "r"((a)[0]), "r"((a)[1]), "r"((a)[2]), "r"((a)[3]), \
          "r"((b)[0]), "r"((b)[1]))

// ---------------- init / gating / routing (proven) ---------------------------
__global__ void init_kernel() {
    if (threadIdx.x < NE) g_counts[threadIdx.x] = 0;
}

__global__ void gating_kernel(const float* __restrict__ x,
                              const float* __restrict__ Wg,
                              const float* __restrict__ bg) {
    int warp = (blockIdx.x * blockDim.x + threadIdx.x) >> 5;
    int lane = threadIdx.x & 31;
    if (warp >= NB) return;
    const float* xr = x + (size_t)warp * ND;
    float acc[8];
#pragma unroll
    for (int i = 0; i < 8; ++i) acc[i] = 0.f;
#pragma unroll 4
    for (int j = 0; j < ND / 32; ++j) {
        int d = j * 32 + lane;
        float xv = xr[d];
        const float* wr = Wg + (size_t)d * NE;
        float4 w0 = *(const float4*)(wr);
        float4 w1 = *(const float4*)(wr + 4);
        acc[0] += xv * w0.x; acc[1] += xv * w0.y;
        acc[2] += xv * w0.z; acc[3] += xv * w0.w;
        acc[4] += xv * w1.x; acc[5] += xv * w1.y;
        acc[6] += xv * w1.z; acc[7] += xv * w1.w;
    }
#pragma unroll
    for (int i = 0; i < 8; ++i)
#pragma unroll
        for (int off = 16; off > 0; off >>= 1)
            acc[i] += __shfl_xor_sync(0xFFFFFFFFu, acc[i], off);
    if (lane == 0) {
        float l[8];
#pragma unroll
        for (int i = 0; i < 8; ++i) l[i] = acc[i] + bg[i];
        int e0 = 0; float v0 = l[0];
#pragma unroll
        for (int i = 1; i < 8; ++i)
            if (l[i] > v0) { v0 = l[i]; e0 = i; }
        int e1 = -1; float v1 = -1e30f;
#pragma unroll
        for (int i = 0; i < 8; ++i)
            if (i != e0 && l[i] > v1) { v1 = l[i]; e1 = i; }
        float t  = expf(v1 - v0);
        float w0 = 1.f / (1.f + t);
        float w1 = t / (1.f + t);
        g_eidx[warp * 2 + 0] = e0;
        g_eidx[warp * 2 + 1] = e1;
        g_wts[warp * 2 + 0]  = w0;
        g_wts[warp * 2 + 1]  = w1;
        atomicAdd(&g_counts[e0], 1);
        atomicAdd(&g_counts[e1], 1);
    }
}

__global__ void route_build_kernel() {
    if (threadIdx.x == 0 && blockIdx.x == 0) {
        int off = 0, tile = 0;
        for (int e = 0; e < NE; ++e) {
            g_offsets[e] = off;
            g_cursor[e]  = 0;
            int c  = g_counts[e];
            int nt = (c + BM - 1) / BM;
            for (int i = 0; i < nt; ++i) {
                g_tile_expert[tile] = e;
                g_tile_segend[tile] = off + c;
                ++tile;
            }
            off += nt * BM;
        }
        for (; tile < MAX_TILES; ++tile) { g_tile_expert[tile] = -1; g_tile_segend[tile] = 0; }
    }
}

__global__ void assign_kernel() {
    int tid = blockIdx.x * blockDim.x + threadIdx.x;
    if (tid >= NB * 2) return;
    int b = tid >> 1;
    int e = g_eidx[tid];
    int pos = g_offsets[e] + atomicAdd(&g_cursor[e], 1);
    g_pair_token[pos] = b;
    g_pairpos[tid]    = pos;
}

// ---------------- gather x -> fp16 pair rows ---------------------------------
__global__ void gather_kernel(const float* __restrict__ x) {
    const int PER_ROW = ND / 8;
    int idx = blockIdx.x * blockDim.x + threadIdx.x;
    if (idx >= PAD_ROWS * PER_ROW) return;
    int r = idx / PER_ROW;
    int j = idx - r * PER_ROW;
    int rt = r >> 7;
    int tokv = -1;
    if (g_tile_expert[rt] >= 0 && r < g_tile_segend[rt]) tokv = g_pair_token[r];

    ushort h16[8];
    if (tokv >= 0) {
        const float* xp = x + (size_t)tokv * ND + j * 8;
        float4 a = *(const float4*)xp;
        float4 b = *(const float4*)(xp + 4);
        float v[8] = {a.x, a.y, a.z, a.w, b.x, b.y, b.z, b.w};
#pragma unroll
        for (int i = 0; i < 8; ++i)
            h16[i] = __half_as_ushort(__float2half_rn(v[i]));
    } else {
#pragma unroll
        for (int i = 0; i < 8; ++i) h16[i] = 0;
    }
    *(uint4*)(g_a16 + (size_t)r * ND + j * 8) = *(uint4*)h16;
}

// ---------------- weight transpose+convert: W[e][K][N] -> [e][N][K] fp16 -----
template<bool IS_W1>
__global__ void wconv_kernel(const float* __restrict__ W, int K, int N) {
    __shared__ float tile[32][33];
    __half* oh = IS_W1 ? g_w1t_hi : g_w2t_hi;
    __half* ol = IS_W1 ? g_w1t_lo : g_w2t_lo;
    int e = blockIdx.z;
    const float* Win = W + (size_t)e * K * N;
    __half* ohe = oh + (size_t)e * K * N;
    __half* ole = ol + (size_t)e * K * N;
    int n0 = blockIdx.x * 32, k0 = blockIdx.y * 32;
    int tx = threadIdx.x, ty = threadIdx.y;
#pragma unroll
    for (int j = 0; j < 4; ++j)
        tile[ty + j * 8][tx] = Win[(size_t)(k0 + ty + j * 8) * N + n0 + tx];
    __syncthreads();
#pragma unroll
    for (int j = 0; j < 4; ++j) {
        float v = tile[tx][ty + j * 8];
        size_t o = (size_t)(n0 + ty + j * 8) * K + k0 + tx;
        __half h = __float2half_rn(v);
        ohe[o] = h;
        ole[o] = __float2half_rn(v - __half2float(h));
    }
}

// ---------------- lean HMMA GEMM: exact-fp16 A, split-B, 2 products ----------
// 256 threads = 8 warps 2(m) x 4(n); warp tile 64x32.
// A smem [m][k] fp16 (exact); B smem [n][k] fp16 hi/lo (OP_LD stride).
// acc += A*Bh ; acc += A*Bl — per-acc dependent MMAs 4 apart (product-major).
template<int KTOT, bool IS_GEMM1>
__global__ __launch_bounds__(256, 2) void gemm_mma_kernel(
    const float* __restrict__ bias_all,  // b1 or b2 (harness pointer)
    int NTOT) {

    __shared__ __half sA [2][BM * OP_LD];
    __shared__ __half sBh[2][BN * OP_LD];
    __shared__ __half sBl[2][BN * OP_LD];

    const __half* Ain = IS_GEMM1 ? g_a16 : g_h16;
    const __half* Bhi = IS_GEMM1 ? g_w1t_hi : g_w2t_hi;
    const __half* Blo = IS_GEMM1 ? g_w1t_lo : g_w2t_lo;

    int rt = blockIdx.y;
    int e  = g_tile_expert[rt];
    if (e < 0) return;
    int seg_end = g_tile_segend[rt];
    int r0 = rt * BM;
    int n0 = blockIdx.x * BN;

    int t = threadIdx.x;
    int lane = t & 31;
    int warp = t >> 5;
    int m_base = (warp & 1) * 64;
    int n_base = (warp >> 1) * 32;
    int g4   = lane >> 2;   // 0..7
    int tid4 = lane & 3;    // 0..3

    // ---- cp.async loader mapping: thread t -> row t>>1, 16B half t&1 --------
    int row  = t >> 1;
    int half = t & 1;
    const __half* aP  = Ain + (size_t)(r0 + row) * KTOT + half * 8;
    const __half* bPh = Bhi + ((size_t)e * NTOT + n0 + row) * KTOT + half * 8;
    const __half* bPl = Blo + ((size_t)e * NTOT + n0 + row) * KTOT + half * 8;
    uint32_t so = (uint32_t)((row * OP_LD + half * 8) * 2);
    uint32_t uA  = smem_to_u32(sA)  + so;
    uint32_t uBh = smem_to_u32(sBh) + so;
    uint32_t uBl = smem_to_u32(sBl) + so;
    const uint32_t stage_b = BM * OP_LD * 2;

    auto issue = [&](int c, int s) {
        uint32_t off = (uint32_t)s * stage_b;
        size_t go = (size_t)c * BK;
        cp_async16(uA  + off, aP  + go);
        cp_async16(uBh + off, bPh + go);
        cp_async16(uBl + off, bPl + go);
    };

    const float* bias_e = bias_all + (size_t)e * NTOT + n0;

    float acc[4][4][4];
#pragma unroll
    for (int i = 0; i < 4; ++i)
#pragma unroll
        for (int j = 0; j < 4; ++j)
#pragma unroll
            for (int q = 0; q < 4; ++q) acc[i][j][q] = 0.f;

    const int NC = KTOT / BK;

    issue(0, 0); CP_COMMIT();

    for (int c = 0; c < NC; ++c) {
        int s = c & 1;
        if (c + 1 < NC) {
            issue(c + 1, s ^ 1); CP_COMMIT();
            CP_WAIT(1);
        } else {
            CP_WAIT(0);
        }
        __syncthreads();

        const __half* pA  = sA[s];
        const __half* pBh = sBh[s];
        const __half* pBl = sBl[s];

        // B fragments for all j (one 32-bit LDS each)
        uint32_t bh[4][2], bl[4][2];
#pragma unroll
        for (int j = 0; j < 4; ++j) {
            int nrow = (n_base + j * 8 + g4) * OP_LD + tid4 * 2;
            bh[j][0] = *(const uint32_t*)&pBh[nrow];
            bh[j][1] = *(const uint32_t*)&pBh[nrow + 8];
            bl[j][0] = *(const uint32_t*)&pBl[nrow];
            bl[j][1] = *(const uint32_t*)&pBl[nrow + 8];
        }

#pragma unroll
        for (int i = 0; i < 4; ++i) {
            uint32_t fa[4];
            int rlo = (m_base + i * 16 + g4) * OP_LD + tid4 * 2;
            int rhi = rlo + 8 * OP_LD;
            fa[0] = *(const uint32_t*)&pA[rlo];
            fa[1] = *(const uint32_t*)&pA[rhi];
            fa[2] = *(const uint32_t*)&pA[rlo + 8];
            fa[3] = *(const uint32_t*)&pA[rhi + 8];
            // product-major: dependent MMAs to one acc are 4 apart
#pragma unroll
            for (int j = 0; j < 4; ++j) MMA_F16(acc[i][j], fa, bh[j]);
#pragma unroll
            for (int j = 0; j < 4; ++j) MMA_F16(acc[i][j], fa, bl[j]);
        }
        __syncthreads();
    }

    // ---- epilogue: direct from accumulator regs -----------------------------
#pragma unroll
    for (int j = 0; j < 4; ++j) {
        int coll = n_base + j * 8 + tid4 * 2;
        float b0 = bias_e[coll];
        float b1 = bias_e[coll + 1];
        int gcol = n0 + coll;
#pragma unroll
        for (int i = 0; i < 4; ++i) {
            int row0 = r0 + m_base + i * 16 + g4;
            int row1 = row0 + 8;
            float v0 = acc[i][j][0] + b0;
            float v1 = acc[i][j][1] + b1;
            float v2 = acc[i][j][2] + b0;
            float v3 = acc[i][j][3] + b1;
            if (IS_GEMM1) {
                v0 = fmaxf(v0, 0.f); v1 = fmaxf(v1, 0.f);
                v2 = fmaxf(v2, 0.f); v3 = fmaxf(v3, 0.f);
                if (row0 < seg_end) {
                    uint32_t p = (uint32_t)__half_as_ushort(__float2half_rn(v0)) |
                                 ((uint32_t)__half_as_ushort(__float2half_rn(v1)) << 16);
                    *(uint32_t*)(g_h16 + (size_t)row0 * NH + gcol) = p;
                }
                if (row1 < seg_end) {
                    uint32_t p = (uint32_t)__half_as_ushort(__float2half_rn(v2)) |
                                 ((uint32_t)__half_as_ushort(__float2half_rn(v3)) << 16);
                    *(uint32_t*)(g_h16 + (size_t)row1 * NH + gcol) = p;
                }
            } else {
                if (row0 < seg_end) {
                    float2 p; p.x = v0; p.y = v1;
                    *(float2*)(g_outp + (size_t)row0 * ND + gcol) = p;
                }
                if (row1 < seg_end) {
                    float2 p; p.x = v2; p.y = v3;
                    *(float2*)(g_outp + (size_t)row1 * ND + gcol) = p;
                }
            }
        }
    }
}

// ---------------- combine ----------------------------------------------------
__global__ void combine_kernel(float* __restrict__ y) {
    const int QD = ND / 4;
    int tid = blockIdx.x * blockDim.x + threadIdx.x;
    if (tid >= NB * QD) return;
    int b = tid / QD;
    int q = tid - b * QD;
    int p0 = g_pairpos[b * 2 + 0];
    int p1 = g_pairpos[b * 2 + 1];
    float w0 = g_wts[b * 2 + 0];
    float w1 = g_wts[b * 2 + 1];
    float4 o0 = ((const float4*)(g_outp + (size_t)p0 * ND))[q];
    float4 o1 = ((const float4*)(g_outp + (size_t)p1 * ND))[q];
    float4 r;
    r.x = w0 * o0.x + w1 * o1.x;
    r.y = w0 * o0.y + w1 * o1.y;
    r.z = w0 * o0.z + w1 * o1.z;
    r.w = w0 * o0.w + w1 * o1.w;
    ((float4*)y)[tid] = r;
}

// ---------------- launch ------------------------------------------------------
extern "C" void kernel_launch(void* const* d_in, const int* in_sizes, int n_in,
                              void* d_out, int out_size) {
    const float* x  = (const float*)d_in[0];
    const float* Wg = (const float*)d_in[1];
    const float* bg = (const float*)d_in[2];
    const float* W1 = (const float*)d_in[3];
    const float* b1 = (const float*)d_in[4];
    const float* W2 = (const float*)d_in[5];
    const float* b2 = (const float*)d_in[6];
    float* y = (float*)d_out;

    init_kernel<<<1, 32>>>();
    gating_kernel<<<(NB * 32) / 256, 256>>>(x, Wg, bg);
    route_build_kernel<<<1, 1>>>();
    assign_kernel<<<(NB * 2) / 256, 256>>>();

    // one-time conversions
    {
        dim3 g(NH / 32, ND / 32, NE);
        wconv_kernel<true><<<g, dim3(32, 8)>>>(W1, ND, NH);
    }
    {
        dim3 g(ND / 32, NH / 32, NE);
        wconv_kernel<false><<<g, dim3(32, 8)>>>(W2, NH, ND);
    }
    {
        int total = PAD_ROWS * (ND / 8);
        gather_kernel<<<(total + 255) / 256, 256>>>(x);
    }

    // GEMM1: relu(fp16(x)[gather] @ (W1h+W1l) + b1) -> g_h16
    {
        dim3 g(NH / BN, MAX_TILES);
        gemm_mma_kernel<ND, true><<<g, 256>>>(b1, NH);
    }
    // GEMM2: g_h16 @ (W2h+W2l) + b2 -> g_outp
    {
        dim3 g(ND / BN, MAX_TILES);
        gemm_mma_kernel<NH, false><<<g, 256>>>(b2, ND);
    }

    combine_kernel<<<(NB * (ND / 4) + 255) / 256, 256>>>(y);
}

// round 14
// speedup vs baseline: 5.8145x; 1.8813x over previous
#include <cuda_runtime.h>
#include <cuda_fp16.h>
#include <cstdint>
#include <math.h>

#define NB 32768      // tokens
#define ND 768        // model dim
#define NH 3072       // hidden dim
#define NE 8          // experts
#define BM 128
#define BN 128
#define BK 32
#define MAX_TILES ((NB * 2) / BM + NE)   // 520
#define PAD_ROWS (MAX_TILES * BM)        // 66560

#define OP_LD 40      // smem row stride (elements): 32 data + 8 pad = 80B

// ---------------- scratch (device globals; referenced ONLY by name in device
// code — never passed as kernel arguments from host) --------------------------
__device__ __half g_a16[(size_t)PAD_ROWS * ND];    // fp16(x) gathered pair rows
__device__ __half g_h16[(size_t)PAD_ROWS * NH];    // fp16(relu(h)) activations
__device__ float  g_outp[(size_t)PAD_ROWS * ND];   // per-pair expert outputs
__device__ __half g_w1t[(size_t)NE * NH * ND];     // [e][n][k] fp16
__device__ __half g_w2t[(size_t)NE * ND * NH];     // [e][n][k] fp16
__device__ int   g_pair_token[PAD_ROWS];
__device__ int   g_pairpos[NB * 2];
__device__ float g_wts[NB * 2];
__device__ int   g_eidx[NB * 2];
__device__ int   g_counts[NE];
__device__ int   g_cursor[NE];
__device__ int   g_offsets[NE];
__device__ int   g_tile_expert[MAX_TILES];
__device__ int   g_tile_segend[MAX_TILES];

// ---------------- PTX helpers ------------------------------------------------
__device__ __forceinline__ uint32_t smem_to_u32(const void* p) {
    uint32_t a;
    asm("{ .reg .u64 t; cvta.to.shared.u64 t, %1; cvt.u32.u64 %0, t; }"
        : "=r"(a) : "l"(p));
    return a;
}
__device__ __forceinline__ void cp_async16(uint32_t smem, const void* g) {
    asm volatile("cp.async.cg.shared.global [%0], [%1], 16;" :: "r"(smem), "l"(g));
}
#define CP_COMMIT() asm volatile("cp.async.commit_group;" ::: "memory")
#define CP_WAIT(n)  asm volatile("cp.async.wait_group %0;" :: "n"(n) : "memory")

#define MMA_F16(d, a, b) \
    asm volatile("mma.sync.aligned.m16n8k16.row.col.f32.f16.f16.f32 " \
        "{%0,%1,%2,%3}, {%4,%5,%6,%7}, {%8,%9}, {%0,%1,%2,%3};" \
        : "+f"((d)[0]), "+f"((d)[1]), "+f"((d)[2]), "+f"((d)[3]) \
        : "r"((a)[0]), "r"((a)[1]), "r"((a)[2]), "r"((a)[3]), \
          "r"((b)[0]), "r"((b)[1]))

// ---------------- init / gating / routing (proven) ---------------------------
__global__ void init_kernel() {
    if (threadIdx.x < NE) g_counts[threadIdx.x] = 0;
}

__global__ void gating_kernel(const float* __restrict__ x,
                              const float* __restrict__ Wg,
                              const float* __restrict__ bg) {
    int warp = (blockIdx.x * blockDim.x + threadIdx.x) >> 5;
    int lane = threadIdx.x & 31;
    if (warp >= NB) return;
    const float* xr = x + (size_t)warp * ND;
    float acc[8];
#pragma unroll
    for (int i = 0; i < 8; ++i) acc[i] = 0.f;
#pragma unroll 4
    for (int j = 0; j < ND / 32; ++j) {
        int d = j * 32 + lane;
        float xv = xr[d];
        const float* wr = Wg + (size_t)d * NE;
        float4 w0 = *(const float4*)(wr);
        float4 w1 = *(const float4*)(wr + 4);
        acc[0] += xv * w0.x; acc[1] += xv * w0.y;
        acc[2] += xv * w0.z; acc[3] += xv * w0.w;
        acc[4] += xv * w1.x; acc[5] += xv * w1.y;
        acc[6] += xv * w1.z; acc[7] += xv * w1.w;
    }
#pragma unroll
    for (int i = 0; i < 8; ++i)
#pragma unroll
        for (int off = 16; off > 0; off >>= 1)
            acc[i] += __shfl_xor_sync(0xFFFFFFFFu, acc[i], off);
    if (lane == 0) {
        float l[8];
#pragma unroll
        for (int i = 0; i < 8; ++i) l[i] = acc[i] + bg[i];
        int e0 = 0; float v0 = l[0];
#pragma unroll
        for (int i = 1; i < 8; ++i)
            if (l[i] > v0) { v0 = l[i]; e0 = i; }
        int e1 = -1; float v1 = -1e30f;
#pragma unroll
        for (int i = 0; i < 8; ++i)
            if (i != e0 && l[i] > v1) { v1 = l[i]; e1 = i; }
        float t  = expf(v1 - v0);
        float w0 = 1.f / (1.f + t);
        float w1 = t / (1.f + t);
        g_eidx[warp * 2 + 0] = e0;
        g_eidx[warp * 2 + 1] = e1;
        g_wts[warp * 2 + 0]  = w0;
        g_wts[warp * 2 + 1]  = w1;
        atomicAdd(&g_counts[e0], 1);
        atomicAdd(&g_counts[e1], 1);
    }
}

__global__ void route_build_kernel() {
    if (threadIdx.x == 0 && blockIdx.x == 0) {
        int off = 0, tile = 0;
        for (int e = 0; e < NE; ++e) {
            g_offsets[e] = off;
            g_cursor[e]  = 0;
            int c  = g_counts[e];
            int nt = (c + BM - 1) / BM;
            for (int i = 0; i < nt; ++i) {
                g_tile_expert[tile] = e;
                g_tile_segend[tile] = off + c;
                ++tile;
            }
            off += nt * BM;
        }
        for (; tile < MAX_TILES; ++tile) { g_tile_expert[tile] = -1; g_tile_segend[tile] = 0; }
    }
}

__global__ void assign_kernel() {
    int tid = blockIdx.x * blockDim.x + threadIdx.x;
    if (tid >= NB * 2) return;
    int b = tid >> 1;
    int e = g_eidx[tid];
    int pos = g_offsets[e] + atomicAdd(&g_cursor[e], 1);
    g_pair_token[pos] = b;
    g_pairpos[tid]    = pos;
}

// ---------------- gather x -> fp16 pair rows ---------------------------------
__global__ void gather_kernel(const float* __restrict__ x) {
    const int PER_ROW = ND / 8;
    int idx = blockIdx.x * blockDim.x + threadIdx.x;
    if (idx >= PAD_ROWS * PER_ROW) return;
    int r = idx / PER_ROW;
    int j = idx - r * PER_ROW;
    int rt = r >> 7;
    int tokv = -1;
    if (g_tile_expert[rt] >= 0 && r < g_tile_segend[rt]) tokv = g_pair_token[r];

    ushort h16[8];
    if (tokv >= 0) {
        const float* xp = x + (size_t)tokv * ND + j * 8;
        float4 a = *(const float4*)xp;
        float4 b = *(const float4*)(xp + 4);
        float v[8] = {a.x, a.y, a.z, a.w, b.x, b.y, b.z, b.w};
#pragma unroll
        for (int i = 0; i < 8; ++i)
            h16[i] = __half_as_ushort(__float2half_rn(v[i]));
    } else {
#pragma unroll
        for (int i = 0; i < 8; ++i) h16[i] = 0;
    }
    *(uint4*)(g_a16 + (size_t)r * ND + j * 8) = *(uint4*)h16;
}

// ---------------- weight transpose+convert: W[e][K][N] -> [e][N][K] fp16 -----
template<bool IS_W1>
__global__ void wconv_kernel(const float* __restrict__ W, int K, int N) {
    __shared__ float tile[32][33];
    __half* o = IS_W1 ? g_w1t : g_w2t;
    int e = blockIdx.z;
    const float* Win = W + (size_t)e * K * N;
    __half* oe = o + (size_t)e * K * N;
    int n0 = blockIdx.x * 32, k0 = blockIdx.y * 32;
    int tx = threadIdx.x, ty = threadIdx.y;
#pragma unroll
    for (int j = 0; j < 4; ++j)
        tile[ty + j * 8][tx] = Win[(size_t)(k0 + ty + j * 8) * N + n0 + tx];
    __syncthreads();
#pragma unroll
    for (int j = 0; j < 4; ++j) {
        float v = tile[tx][ty + j * 8];
        oe[(size_t)(n0 + ty + j * 8) * K + k0 + tx] = __float2half_rn(v);
    }
}

// ---------------- single-product fp16 HMMA GEMM ------------------------------
// 256 threads = 8 warps 2(m) x 4(n); warp tile 64x32; BK=32 (2 k-steps).
// A smem [m][k] fp16; B smem [n][k] fp16 (OP_LD=40 stride, conflict-free).
// acc += A*B only — MMA count halved vs R13; per-acc dependent MMAs 4 apart.
template<int KTOT, bool IS_GEMM1>
__global__ __launch_bounds__(256, 2) void gemm_mma_kernel(
    const float* __restrict__ bias_all,  // b1 or b2 (harness pointer)
    int NTOT) {

    __shared__ __half sA[2][BM * OP_LD];
    __shared__ __half sB[2][BN * OP_LD];

    const __half* Ain = IS_GEMM1 ? g_a16 : g_h16;
    const __half* Bin = IS_GEMM1 ? g_w1t : g_w2t;

    int rt = blockIdx.y;
    int e  = g_tile_expert[rt];
    if (e < 0) return;
    int seg_end = g_tile_segend[rt];
    int r0 = rt * BM;
    int n0 = blockIdx.x * BN;

    int t = threadIdx.x;
    int lane = t & 31;
    int warp = t >> 5;
    int m_base = (warp & 1) * 64;
    int n_base = (warp >> 1) * 32;
    int g4   = lane >> 2;   // 0..7
    int tid4 = lane & 3;    // 0..3

    // ---- cp.async loader: 512 16B-chunks per operand tile, 2 per thread -----
    // idx = t + r*256 : row = idx>>2 (0..127), chunk = idx&3 (16B within 64B row)
    const float* bias_e = bias_all + (size_t)e * NTOT + n0;
    uint32_t uA = smem_to_u32(sA);
    uint32_t uB = smem_to_u32(sB);
    const uint32_t stage_b = BM * OP_LD * 2;   // bytes per stage

    auto issue = [&](int c, int s) {
        uint32_t off = (uint32_t)s * stage_b;
        int koff = c * BK;
#pragma unroll
        for (int r = 0; r < 2; ++r) {
            int idx = t + r * 256;
            int row = idx >> 2;
            int ch  = idx & 3;
            uint32_t so = (uint32_t)(row * (OP_LD * 2) + ch * 16);
            cp_async16(uA + off + so,
                       Ain + (size_t)(r0 + row) * KTOT + koff + ch * 8);
            cp_async16(uB + off + so,
                       Bin + ((size_t)e * NTOT + n0 + row) * KTOT + koff + ch * 8);
        }
    };

    float acc[4][4][4];
#pragma unroll
    for (int i = 0; i < 4; ++i)
#pragma unroll
        for (int j = 0; j < 4; ++j)
#pragma unroll
            for (int q = 0; q < 4; ++q) acc[i][j][q] = 0.f;

    const int NC = KTOT / BK;

    issue(0, 0); CP_COMMIT();

    for (int c = 0; c < NC; ++c) {
        int s = c & 1;
        if (c + 1 < NC) {
            issue(c + 1, s ^ 1); CP_COMMIT();
            CP_WAIT(1);
        } else {
            CP_WAIT(0);
        }
        __syncthreads();

        const __half* pA = sA[s];
        const __half* pB = sB[s];

#pragma unroll
        for (int ks = 0; ks < 2; ++ks) {
            int kadd = ks * 16;
            // B fragments for all j (one 32-bit LDS each)
            uint32_t fb[4][2];
#pragma unroll
            for (int j = 0; j < 4; ++j) {
                int nrow = (n_base + j * 8 + g4) * OP_LD + kadd + tid4 * 2;
                fb[j][0] = *(const uint32_t*)&pB[nrow];
                fb[j][1] = *(const uint32_t*)&pB[nrow + 8];
            }
#pragma unroll
            for (int i = 0; i < 4; ++i) {
                uint32_t fa[4];
                int rlo = (m_base + i * 16 + g4) * OP_LD + kadd + tid4 * 2;
                int rhi = rlo + 8 * OP_LD;
                fa[0] = *(const uint32_t*)&pA[rlo];
                fa[1] = *(const uint32_t*)&pA[rhi];
                fa[2] = *(const uint32_t*)&pA[rlo + 8];
                fa[3] = *(const uint32_t*)&pA[rhi + 8];
#pragma unroll
                for (int j = 0; j < 4; ++j) MMA_F16(acc[i][j], fa, fb[j]);
            }
        }
        __syncthreads();
    }

    // ---- epilogue: direct from accumulator regs -----------------------------
#pragma unroll
    for (int j = 0; j < 4; ++j) {
        int coll = n_base + j * 8 + tid4 * 2;
        float b0 = bias_e[coll];
        float b1 = bias_e[coll + 1];
        int gcol = n0 + coll;
#pragma unroll
        for (int i = 0; i < 4; ++i) {
            int row0 = r0 + m_base + i * 16 + g4;
            int row1 = row0 + 8;
            float v0 = acc[i][j][0] + b0;
            float v1 = acc[i][j][1] + b1;
            float v2 = acc[i][j][2] + b0;
            float v3 = acc[i][j][3] + b1;
            if (IS_GEMM1) {
                v0 = fmaxf(v0, 0.f); v1 = fmaxf(v1, 0.f);
                v2 = fmaxf(v2, 0.f); v3 = fmaxf(v3, 0.f);
                if (row0 < seg_end) {
                    uint32_t p = (uint32_t)__half_as_ushort(__float2half_rn(v0)) |
                                 ((uint32_t)__half_as_ushort(__float2half_rn(v1)) << 16);
                    *(uint32_t*)(g_h16 + (size_t)row0 * NH + gcol) = p;
                }
                if (row1 < seg_end) {
                    uint32_t p = (uint32_t)__half_as_ushort(__float2half_rn(v2)) |
                                 ((uint32_t)__half_as_ushort(__float2half_rn(v3)) << 16);
                    *(uint32_t*)(g_h16 + (size_t)row1 * NH + gcol) = p;
                }
            } else {
                if (row0 < seg_end) {
                    float2 p; p.x = v0; p.y = v1;
                    *(float2*)(g_outp + (size_t)row0 * ND + gcol) = p;
                }
                if (row1 < seg_end) {
                    float2 p; p.x = v2; p.y = v3;
                    *(float2*)(g_outp + (size_t)row1 * ND + gcol) = p;
                }
            }
        }
    }
}

// ---------------- combine ----------------------------------------------------
__global__ void combine_kernel(float* __restrict__ y) {
    const int QD = ND / 4;
    int tid = blockIdx.x * blockDim.x + threadIdx.x;
    if (tid >= NB * QD) return;
    int b = tid / QD;
    int q = tid - b * QD;
    int p0 = g_pairpos[b * 2 + 0];
    int p1 = g_pairpos[b * 2 + 1];
    float w0 = g_wts[b * 2 + 0];
    float w1 = g_wts[b * 2 + 1];
    float4 o0 = ((const float4*)(g_outp + (size_t)p0 * ND))[q];
    float4 o1 = ((const float4*)(g_outp + (size_t)p1 * ND))[q];
    float4 r;
    r.x = w0 * o0.x + w1 * o1.x;
    r.y = w0 * o0.y + w1 * o1.y;
    r.z = w0 * o0.z + w1 * o1.z;
    r.w = w0 * o0.w + w1 * o1.w;
    ((float4*)y)[tid] = r;
}

// ---------------- launch ------------------------------------------------------
extern "C" void kernel_launch(void* const* d_in, const int* in_sizes, int n_in,
                              void* d_out, int out_size) {
    const float* x  = (const float*)d_in[0];
    const float* Wg = (const float*)d_in[1];
    const float* bg = (const float*)d_in[2];
    const float* W1 = (const float*)d_in[3];
    const float* b1 = (const float*)d_in[4];
    const float* W2 = (const float*)d_in[5];
    const float* b2 = (const float*)d_in[6];
    float* y = (float*)d_out;

    init_kernel<<<1, 32>>>();
    gating_kernel<<<(NB * 32) / 256, 256>>>(x, Wg, bg);
    route_build_kernel<<<1, 1>>>();
    assign_kernel<<<(NB * 2) / 256, 256>>>();

    // one-time conversions
    {
        dim3 g(NH / 32, ND / 32, NE);
        wconv_kernel<true><<<g, dim3(32, 8)>>>(W1, ND, NH);
    }
    {
        dim3 g(ND / 32, NH / 32, NE);
        wconv_kernel<false><<<g, dim3(32, 8)>>>(W2, NH, ND);
    }
    {
        int total = PAD_ROWS * (ND / 8);
        gather_kernel<<<(total + 255) / 256, 256>>>(x);
    }

    // GEMM1: relu(fp16(x)[gather] @ fp16(W1) + b1) -> g_h16
    {
        dim3 g(NH / BN, MAX_TILES);
        gemm_mma_kernel<ND, true><<<g, 256>>>(b1, NH);
    }
    // GEMM2: g_h16 @ fp16(W2) + b2 -> g_outp
    {
        dim3 g(ND / BN, MAX_TILES);
        gemm_mma_kernel<NH, false><<<g, 256>>>(b2, ND);
    }

    combine_kernel<<<(NB * (ND / 4) + 255) / 256, 256>>>(y);
}